// round 9
// baseline (speedup 1.0000x reference)
#include <cuda_runtime.h>
#include <cuda_bf16.h>
#include <stdint.h>

// ---------------- problem constants ----------------
#define NATOMS   16384
#define NSEL     4096
#define NODE_F   8
#define HID      128
#define HEADS    8
#define DH       16
#define OUTD     256
#define NLIG     32
#define NBINS    65536

#define TQ 64      // queries per attention block (16 per warp)
#define TK 128     // keys per smem tile
#define KPAD 24    // smem row stride in bf16 (48B: 16B-aligned, ldmatrix conflict-free)

typedef unsigned long long ull;

// ---------------- packed f32x2 helpers (Blackwell FFMA2 path) ----------------
__device__ __forceinline__ ull f2_pack(float lo, float hi) {
    ull r; asm("mov.b64 %0, {%1, %2};" : "=l"(r) : "f"(lo), "f"(hi)); return r;
}
__device__ __forceinline__ void f2_unpack(ull v, float& lo, float& hi) {
    asm("mov.b64 {%0, %1}, %2;" : "=f"(lo), "=f"(hi) : "l"(v));
}
__device__ __forceinline__ ull f2_add(ull a, ull b) {
    ull r; asm("add.rn.f32x2 %0, %1, %2;" : "=l"(r) : "l"(a), "l"(b)); return r;
}
__device__ __forceinline__ ull f2_fma(ull a, ull b, ull c) {
    ull r; asm("fma.rn.f32x2 %0, %1, %2, %3;" : "=l"(r) : "l"(a), "l"(b), "l"(c)); return r;
}
__device__ __forceinline__ float ex2(float x) {
    float r; asm("ex2.approx.f32 %0, %1;" : "=f"(r) : "f"(x)); return r;
}

// ---------------- tensor-core helpers ----------------
__device__ __forceinline__ unsigned scvt(const void* p) {
    return (unsigned)__cvta_generic_to_shared(p);
}
__device__ __forceinline__ void ldm_x4(unsigned* r, unsigned a) {
    asm volatile("ldmatrix.sync.aligned.m8n8.x4.shared.b16 {%0,%1,%2,%3}, [%4];"
        : "=r"(r[0]), "=r"(r[1]), "=r"(r[2]), "=r"(r[3]) : "r"(a));
}
__device__ __forceinline__ void ldm_x2(unsigned* r, unsigned a) {
    asm volatile("ldmatrix.sync.aligned.m8n8.x2.shared.b16 {%0,%1}, [%2];"
        : "=r"(r[0]), "=r"(r[1]) : "r"(a));
}
__device__ __forceinline__ void ldm_x2t(unsigned* r, unsigned a) {
    asm volatile("ldmatrix.sync.aligned.m8n8.x2.trans.shared.b16 {%0,%1}, [%2];"
        : "=r"(r[0]), "=r"(r[1]) : "r"(a));
}
__device__ __forceinline__ void mma16816(float* d, const unsigned* a, const unsigned* b) {
    asm volatile(
        "mma.sync.aligned.m16n8k16.row.col.f32.bf16.bf16.f32 "
        "{%0,%1,%2,%3}, {%4,%5,%6,%7}, {%8,%9}, {%0,%1,%2,%3};"
        : "+f"(d[0]), "+f"(d[1]), "+f"(d[2]), "+f"(d[3])
        : "r"(a[0]), "r"(a[1]), "r"(a[2]), "r"(a[3]), "r"(b[0]), "r"(b[1]));
}
__device__ __forceinline__ unsigned cvt_bf16x2(float lo, float hi) {
    unsigned r;
    asm("cvt.rn.bf16x2.f32 %0, %1, %2;" : "=r"(r) : "f"(hi), "f"(lo));  // d.hi=%1, d.lo=%2
    return r;
}

// ---------------- scratch (static device memory; no allocation) ----------------
__device__ float    g_sq[NATOMS];
__device__ float    g_s0[NATOMS];
__device__ int      g_cnt[NATOMS];
__device__ unsigned g_keys[NATOMS];
__device__ unsigned g_hist[NBINS];
__device__ int      g_H;
__device__ int      g_r;
__device__ int      g_m;
__device__ int      g_done;
__device__ ull      g_bbuf[NATOMS];
__device__ int      g_sel[NATOMS];
__device__ int      g_idx[NSEL];
__device__ __align__(16) __nv_bfloat16 g_qh[NSEL * HID];  // q * scale*log2e, hi part
__device__ __align__(16) __nv_bfloat16 g_ql[NSEL * HID];  // q residual
__device__ __align__(16) __nv_bfloat16 g_kh[NSEL * HID];  // k hi part
__device__ __align__(16) __nv_bfloat16 g_kl[NSEL * HID];  // k residual
__device__ __align__(16) __nv_bfloat16 g_vh[NSEL * HID];  // V hi part
__device__ __align__(16) __nv_bfloat16 g_vl[NSEL * HID];  // V residual
__device__ __align__(16) float g_av[NSEL * HID];
__device__ float    g_mav[HID];

// ---------------- 0: init (zero hist/cnt + ligand center + per-atom base) ----------------
__global__ void k_init(const float* __restrict__ lig, const float* __restrict__ pos) {
    __shared__ float c3[3];
    int t = threadIdx.x;
    if (t < 32) {
        float x = lig[t * 3 + 0], y = lig[t * 3 + 1], z = lig[t * 3 + 2];
        #pragma unroll
        for (int o = 16; o > 0; o >>= 1) {
            x += __shfl_down_sync(0xFFFFFFFFu, x, o);
            y += __shfl_down_sync(0xFFFFFFFFu, y, o);
            z += __shfl_down_sync(0xFFFFFFFFu, z, o);
        }
        if (t == 0) {
            c3[0] = x * (1.0f / NLIG);
            c3[1] = y * (1.0f / NLIG);
            c3[2] = z * (1.0f / NLIG);
        }
    }
    __syncthreads();
    int gi = blockIdx.x * 256 + t;
    if (gi < NBINS) g_hist[gi] = 0;
    int ci = gi - NBINS;
    if (ci >= 0 && ci < NATOMS) g_cnt[ci] = 0;
    if (gi == 0) { g_m = 0; g_done = 0; }
    if (gi < NATOMS) {
        float x = pos[gi * 3 + 0], y = pos[gi * 3 + 1], z = pos[gi * 3 + 2];
        g_sq[gi] = fmaf(z, z, fmaf(y, y, x * x));
        float dx = x - c3[0], dy = y - c3[1], dz = z - c3[2];
        float d = sqrtf(fmaf(dz, dz, fmaf(dy, dy, dx * dx)));
        g_s0[gi] = 1.0f / (1.0f + d / 5.0f);
    }
}

// ---------------- 1: neighbor counting, FFMA2-packed (2 j-atoms per iter) ----------------
__global__ __launch_bounds__(256) void k_neighbor(const float* __restrict__ pos) {
    __shared__ ull sX[128], sY[128], sZ[128], sW[128];
    int tid = threadIdx.x;
    int i = blockIdx.x * 256 + tid;
    float px = pos[i * 3 + 0], py = pos[i * 3 + 1], pz = pos[i * 3 + 2];
    float ci = 4.5f - 0.5f * g_sq[i];
    ull px2 = f2_pack(px, px), py2 = f2_pack(py, py), pz2 = f2_pack(pz, pz);
    ull ci2 = f2_pack(ci, ci);
    float* fX = (float*)sX; float* fY = (float*)sY; float* fZ = (float*)sZ; float* fW = (float*)sW;
    int cnt = 0;
    int j0 = blockIdx.y * 2048;
    for (int jt = 0; jt < 8; jt++) {
        int j = j0 + jt * 256 + tid;
        fX[tid] = pos[j * 3 + 0];
        fY[tid] = pos[j * 3 + 1];
        fZ[tid] = pos[j * 3 + 2];
        fW[tid] = -0.5f * g_sq[j];
        __syncthreads();
        #pragma unroll 4
        for (int jp = 0; jp < 128; jp++) {
            ull base = f2_add(sW[jp], ci2);
            ull v = f2_fma(px2, sX[jp], f2_fma(py2, sY[jp], f2_fma(pz2, sZ[jp], base)));
            float vlo, vhi; f2_unpack(v, vlo, vhi);
            cnt += (vlo > 0.0f);
            cnt += (vhi > 0.0f);
        }
        __syncthreads();
    }
    atomicAdd(&g_cnt[i], cnt);
}

// ---------------- 2: final scores -> sortable keys + histogram ----------------
__global__ void k_scorekey() {
    int i = blockIdx.x * blockDim.x + threadIdx.x;
    if (i >= NATOMS) return;
    float surface = 1.0f / (float)g_cnt[i];
    float s = g_s0[i] + 0.5f * surface;
    unsigned key = __float_as_uint(s);
    g_keys[i] = key;
    atomicAdd(&g_hist[key >> 16], 1u);
}

// ---------------- 3: threshold bin ----------------
__global__ void k_scan() {
    __shared__ unsigned csum[256];
    int t = threadIdx.x;
    unsigned s = 0;
    for (int b = t * 256; b < (t + 1) * 256; b++) s += g_hist[b];
    csum[t] = s;
    __syncthreads();
    if (t == 0) {
        unsigned g = 0;
        int chunk = 255;
        for (; chunk > 0; chunk--) {
            if (g + csum[chunk] >= (unsigned)NSEL) break;
            g += csum[chunk];
        }
        int H = chunk * 256;
        unsigned r = 1;
        for (int b = chunk * 256 + 255; b >= chunk * 256; b--) {
            unsigned c = g_hist[b];
            if (g + c >= (unsigned)NSEL) { H = b; r = (unsigned)NSEL - g; break; }
            g += c;
        }
        g_H = H;
        g_r = (int)r;
    }
}

// ---------------- 4: boundary-bin elements ----------------
__global__ void k_boundary() {
    int i = blockIdx.x * blockDim.x + threadIdx.x;
    if (i >= NATOMS) return;
    unsigned key = g_keys[i];
    if ((int)(key >> 16) == g_H) {
        int p = atomicAdd(&g_m, 1);
        g_bbuf[p] = ((ull)key << 32) | (ull)(0xFFFFFFFFu - (unsigned)i);
    }
}

// ---------------- 5: selection flags ----------------
__global__ void k_flags() {
    int i = blockIdx.x * blockDim.x + threadIdx.x;
    if (i >= NATOMS) return;
    unsigned key = g_keys[i];
    int hi = (int)(key >> 16);
    int s = 0;
    if (hi > g_H) s = 1;
    else if (hi == g_H) {
        ull mine = ((ull)key << 32) | (ull)(0xFFFFFFFFu - (unsigned)i);
        int m = g_m, cnt = 0, r = g_r;
        for (int t = 0; t < m; t++) cnt += (g_bbuf[t] > mine);
        if (cnt < r) s = 1;
    }
    g_sel[i] = s;
}

// ---------------- 6: single-pass deterministic compaction ----------------
__global__ __launch_bounds__(256) void k_compact_all() {
    __shared__ int sc[256];
    __shared__ int s_off;
    int t = threadIdx.x, b = blockIdx.x;
    int pre = b * 256;
    int s = 0;
    for (int j = t; j < pre; j += 256) s += g_sel[j];
    sc[t] = s;
    __syncthreads();
    for (int o = 128; o > 0; o >>= 1) {
        if (t < o) sc[t] += sc[t + o];
        __syncthreads();
    }
    if (t == 0) s_off = sc[0];
    __syncthreads();
    int i = pre + t;
    int f = g_sel[i];
    sc[t] = f;
    __syncthreads();
    for (int o = 1; o < 256; o <<= 1) {
        int v = (t >= o) ? sc[t - o] : 0;
        __syncthreads();
        sc[t] += v;
        __syncthreads();
    }
    if (f) g_idx[s_off + sc[t] - 1] = i;
}

// ---------------- 7: gather + embed + QKV (16 rows/block; bf16 hi/lo outputs) ----------------
__global__ __launch_bounds__(256) void k_qkv(
    const float* __restrict__ x,
    const float* __restrict__ Wn, const float* __restrict__ bn,
    const float* __restrict__ Wq, const float* __restrict__ bq,
    const float* __restrict__ Wk, const float* __restrict__ bk,
    const float* __restrict__ Wv, const float* __restrict__ bv)
{
    __shared__ float hs[16][HID];
    int t = threadIdx.x;
    int c = t & 127;          // column
    int half = t >> 7;        // 0/1 -> rows 0-7 / 8-15
    int r0 = blockIdx.x * 16;
    #pragma unroll
    for (int k = 0; k < 8; k++) {
        int rr = half * 8 + k;
        int row = g_idx[r0 + rr];
        const float* xr = x + row * NODE_F;
        float acc = bn[c];
        #pragma unroll
        for (int f = 0; f < NODE_F; f++) acc = fmaf(__ldg(xr + f), Wn[f * HID + c], acc);
        hs[rr][c] = acc;
    }
    __syncthreads();
    float aq[8], ak[8], av[8];
    #pragma unroll
    for (int rr = 0; rr < 8; rr++) { aq[rr] = bq[c]; ak[rr] = bk[c]; av[rr] = bv[c]; }
    for (int d = 0; d < HID; d++) {
        float wq = Wq[d * HID + c], wk = Wk[d * HID + c], wv = Wv[d * HID + c];
        #pragma unroll
        for (int rr = 0; rr < 8; rr++) {
            float h = hs[half * 8 + rr][d];
            aq[rr] = fmaf(h, wq, aq[rr]);
            ak[rr] = fmaf(h, wk, ak[rr]);
            av[rr] = fmaf(h, wv, av[rr]);
        }
    }
    const float cs = 0.25f * 1.4426950408889634f;  // scale * log2(e), folded into Q
    #pragma unroll
    for (int rr = 0; rr < 8; rr++) {
        int o = (r0 + half * 8 + rr) * HID + c;
        float qs = aq[rr] * cs;
        __nv_bfloat16 qhi = __float2bfloat16(qs);
        g_qh[o] = qhi;
        g_ql[o] = __float2bfloat16(qs - __bfloat162float(qhi));
        float kf = ak[rr];
        __nv_bfloat16 khi = __float2bfloat16(kf);
        g_kh[o] = khi;
        g_kl[o] = __float2bfloat16(kf - __bfloat162float(khi));
        float vf = av[rr];
        __nv_bfloat16 vhi = __float2bfloat16(vf);
        g_vh[o] = vhi;
        g_vl[o] = __float2bfloat16(vf - __bfloat162float(vhi));
    }
}

// ---------------- 8: tensor-core attention (full hi/lo split — proven R7 numerics) ----------------
// S = Qhi·Khi + Qhi·Klo + Qlo·Khi (~fp32 logits); p = ex2(S);
// O = P·Vhi + P·Vlo. Both Q/K and V residuals are REQUIRED: dropping either
// leaves a query-independent systematic error that survives the mean pool
// (measured: 1.5e-3 both times). No max-subtraction: logits ~ N(0,1).
__global__ __launch_bounds__(128) void k_attn_tc() {
    __shared__ __align__(16) __nv_bfloat16 sKh[TK][KPAD];
    __shared__ __align__(16) __nv_bfloat16 sKl[TK][KPAD];
    __shared__ __align__(16) __nv_bfloat16 sVh[TK][KPAD];
    __shared__ __align__(16) __nv_bfloat16 sVl[TK][KPAD];

    int h    = blockIdx.y;
    int q0   = blockIdx.x * TQ;
    int tid  = threadIdx.x;
    int warp = tid >> 5;
    int lane = tid & 31;

    // stage Q tile (64 rows x 16 cols, hi+lo) into K buffers, ldmatrix to regs
    {
        int row = tid >> 1, half = tid & 1;
        const uint4* sh = (const uint4*)(g_qh + (q0 + row) * HID + h * DH + half * 8);
        const uint4* sl = (const uint4*)(g_ql + (q0 + row) * HID + h * DH + half * 8);
        *(uint4*)&sKh[row][half * 8] = *sh;
        *(uint4*)&sKl[row][half * 8] = *sl;
    }
    __syncthreads();
    unsigned a_hi[4], a_lo[4];
    {
        int mrow = warp * 16 + ((lane >> 3) & 1) * 8 + (lane & 7);
        unsigned coff = (lane >> 4) * 16;
        ldm_x4(a_hi, scvt(&sKh[mrow][0]) + coff);
        ldm_x4(a_lo, scvt(&sKl[mrow][0]) + coff);
    }
    __syncthreads();

    float o[8];
    #pragma unroll
    for (int i = 0; i < 8; i++) o[i] = 0.0f;
    float l0 = 0.0f, l1 = 0.0f;

    int brow8  = lane & 7;                            // QK B: 8 key rows, d halves
    unsigned bcoff = ((lane >> 3) & 1) * 16;
    int vrow16 = (lane & 7) + ((lane >> 3) & 1) * 8;  // PV B: 16 key rows

    for (int kt = 0; kt < NSEL / TK; kt++) {
        {
            int row = tid;  // 128 rows
            int src = (kt * TK + row) * HID + h * DH;
            const uint4* kh = (const uint4*)(g_kh + src);
            const uint4* kl = (const uint4*)(g_kl + src);
            const uint4* vh = (const uint4*)(g_vh + src);
            const uint4* vl = (const uint4*)(g_vl + src);
            *(uint4*)&sKh[row][0] = kh[0]; *(uint4*)&sKh[row][8] = kh[1];
            *(uint4*)&sKl[row][0] = kl[0]; *(uint4*)&sKl[row][8] = kl[1];
            *(uint4*)&sVh[row][0] = vh[0]; *(uint4*)&sVh[row][8] = vh[1];
            *(uint4*)&sVl[row][0] = vl[0]; *(uint4*)&sVl[row][8] = vl[1];
        }
        __syncthreads();

        #pragma unroll
        for (int g16 = 0; g16 < TK / 16; g16++) {
            float S[8];
            #pragma unroll
            for (int i = 0; i < 8; i++) S[i] = 0.0f;
            #pragma unroll
            for (int half8 = 0; half8 < 2; half8++) {
                int kb = g16 * 16 + half8 * 8 + brow8;
                unsigned bh[2], bl[2];
                ldm_x2(bh, scvt(&sKh[kb][0]) + bcoff);
                ldm_x2(bl, scvt(&sKl[kb][0]) + bcoff);
                float* Sd = S + half8 * 4;
                mma16816(Sd, a_hi, bh);
                mma16816(Sd, a_hi, bl);
                mma16816(Sd, a_lo, bh);
            }
            float p0 = ex2(S[0]), p1 = ex2(S[1]), p2 = ex2(S[2]), p3 = ex2(S[3]);
            float p4 = ex2(S[4]), p5 = ex2(S[5]), p6 = ex2(S[6]), p7 = ex2(S[7]);
            l0 += (p0 + p1) + (p4 + p5);   // D rows r0
            l1 += (p2 + p3) + (p6 + p7);   // D rows r0+8
            unsigned pa[4];
            pa[0] = cvt_bf16x2(p0, p1);
            pa[1] = cvt_bf16x2(p2, p3);
            pa[2] = cvt_bf16x2(p4, p5);
            pa[3] = cvt_bf16x2(p6, p7);
            int vr = g16 * 16 + vrow16;
            #pragma unroll
            for (int dh2 = 0; dh2 < 2; dh2++) {
                unsigned bvh[2], bvl[2];
                ldm_x2t(bvh, scvt(&sVh[vr][dh2 * 8]));
                ldm_x2t(bvl, scvt(&sVl[vr][dh2 * 8]));
                mma16816(o + dh2 * 4, pa, bvh);
                mma16816(o + dh2 * 4, pa, bvl);
            }
        }
        __syncthreads();
    }

    l0 += __shfl_xor_sync(0xFFFFFFFFu, l0, 1);
    l0 += __shfl_xor_sync(0xFFFFFFFFu, l0, 2);
    l1 += __shfl_xor_sync(0xFFFFFFFFu, l1, 1);
    l1 += __shfl_xor_sync(0xFFFFFFFFu, l1, 2);
    float inv0 = 1.0f / l0, inv1 = 1.0f / l1;

    int r0c = lane >> 2;
    int cc  = (lane & 3) * 2;
    int row0 = q0 + warp * 16 + r0c;
    int row1 = row0 + 8;
    float* d0 = g_av + row0 * HID + h * DH;
    float* d1 = g_av + row1 * HID + h * DH;
    d0[cc]     = o[0] * inv0;  d0[cc + 1] = o[1] * inv0;
    d1[cc]     = o[2] * inv1;  d1[cc + 1] = o[3] * inv1;
    d0[cc + 8] = o[4] * inv0;  d0[cc + 9] = o[5] * inv0;
    d1[cc + 8] = o[6] * inv1;  d1[cc + 9] = o[7] * inv1;
}

// ---------------- 9: column mean + (last block) Wo/MLP head ----------------
__global__ __launch_bounds__(256) void k_colsum_final(
    const float* __restrict__ Wo, const float* __restrict__ bo,
    const float* __restrict__ W1, const float* __restrict__ b1,
    const float* __restrict__ W2, const float* __restrict__ b2,
    float* __restrict__ out)
{
    __shared__ float sm[256];
    __shared__ int is_last;
    int col = blockIdx.x;
    int t = threadIdx.x;
    float s = 0.0f;
    for (int r = t; r < NSEL; r += 256) s += g_av[r * HID + col];
    sm[t] = s;
    __syncthreads();
    for (int o = 128; o > 0; o >>= 1) {
        if (t < o) sm[t] += sm[t + o];
        __syncthreads();
    }
    if (t == 0) {
        g_mav[col] = sm[0] * (1.0f / NSEL);
        __threadfence();
        is_last = (atomicAdd(&g_done, 1) == HID - 1);
    }
    __syncthreads();
    if (!is_last) return;

    __shared__ float mav[HID];
    __shared__ float pooled[HID];
    __shared__ float t1[OUTD];
    if (t < HID) mav[t] = g_mav[t];
    __syncthreads();
    if (t < HID) {
        float acc = bo[t];
        for (int d = 0; d < HID; d++) acc = fmaf(mav[d], Wo[d * HID + t], acc);
        pooled[t] = acc;
    }
    __syncthreads();
    {
        float acc = b1[t];
        for (int d = 0; d < HID; d++) acc = fmaf(pooled[d], W1[d * OUTD + t], acc);
        t1[t] = fmaxf(acc, 0.0f);
    }
    __syncthreads();
    {
        float acc = b2[t];
        for (int d = 0; d < OUTD; d++) acc = fmaf(t1[d], W2[d * OUTD + t], acc);
        out[t] = acc;
    }
}

// ---------------- launcher ----------------
extern "C" void kernel_launch(void* const* d_in, const int* in_sizes, int n_in,
                              void* d_out, int out_size)
{
    const float* x    = (const float*)d_in[0];
    const float* pos  = (const float*)d_in[1];
    const float* lig  = (const float*)d_in[2];
    const float* Wn   = (const float*)d_in[3];
    const float* bn   = (const float*)d_in[4];
    const float* Wq   = (const float*)d_in[5];
    const float* bq   = (const float*)d_in[6];
    const float* Wk   = (const float*)d_in[7];
    const float* bk   = (const float*)d_in[8];
    const float* Wv   = (const float*)d_in[9];
    const float* bv   = (const float*)d_in[10];
    const float* Wo   = (const float*)d_in[11];
    const float* bo   = (const float*)d_in[12];
    const float* W1   = (const float*)d_in[13];
    const float* b1   = (const float*)d_in[14];
    const float* W2   = (const float*)d_in[15];
    const float* b2   = (const float*)d_in[16];
    float* out = (float*)d_out;

    k_init<<<(NBINS + NATOMS) / 256, 256>>>(lig, pos);
    k_neighbor<<<dim3(NATOMS / 256, 8), 256>>>(pos);
    k_scorekey<<<NATOMS / 256, 256>>>();
    k_scan<<<1, 256>>>();
    k_boundary<<<NATOMS / 256, 256>>>();
    k_flags<<<NATOMS / 256, 256>>>();
    k_compact_all<<<64, 256>>>();
    k_qkv<<<NSEL / 16, 256>>>(x, Wn, bn, Wq, bq, Wk, bk, Wv, bv);
    k_attn_tc<<<dim3(NSEL / TQ, HEADS), 128>>>();
    k_colsum_final<<<HID, 256>>>(Wo, bo, W1, b1, W2, b2, out);
}

// round 10
// speedup vs baseline: 1.1149x; 1.1149x over previous
#include <cuda_runtime.h>
#include <cuda_bf16.h>
#include <stdint.h>

// ---------------- problem constants ----------------
#define NATOMS   16384
#define NSEL     4096
#define NODE_F   8
#define HID      128
#define HEADS    8
#define DH       16
#define OUTD     256
#define NLIG     32
#define NBINS    65536
#define NCHUNK   1024     // coarse chunks of 64 fine bins

#define TQ 64      // queries per attention block (16 per warp)
#define TK 128     // keys per smem tile
#define KPAD 24    // smem row stride in bf16 (48B: 16B-aligned, ldmatrix conflict-free)

typedef unsigned long long ull;

// ---------------- packed f32x2 helpers (Blackwell FFMA2 path) ----------------
__device__ __forceinline__ ull f2_pack(float lo, float hi) {
    ull r; asm("mov.b64 %0, {%1, %2};" : "=l"(r) : "f"(lo), "f"(hi)); return r;
}
__device__ __forceinline__ void f2_unpack(ull v, float& lo, float& hi) {
    asm("mov.b64 {%0, %1}, %2;" : "=f"(lo), "=f"(hi) : "l"(v));
}
__device__ __forceinline__ ull f2_add(ull a, ull b) {
    ull r; asm("add.rn.f32x2 %0, %1, %2;" : "=l"(r) : "l"(a), "l"(b)); return r;
}
__device__ __forceinline__ ull f2_fma(ull a, ull b, ull c) {
    ull r; asm("fma.rn.f32x2 %0, %1, %2, %3;" : "=l"(r) : "l"(a), "l"(b), "l"(c)); return r;
}
__device__ __forceinline__ float ex2(float x) {
    float r; asm("ex2.approx.f32 %0, %1;" : "=f"(r) : "f"(x)); return r;
}

// ---------------- tensor-core helpers ----------------
__device__ __forceinline__ unsigned scvt(const void* p) {
    return (unsigned)__cvta_generic_to_shared(p);
}
__device__ __forceinline__ void ldm_x4(unsigned* r, unsigned a) {
    asm volatile("ldmatrix.sync.aligned.m8n8.x4.shared.b16 {%0,%1,%2,%3}, [%4];"
        : "=r"(r[0]), "=r"(r[1]), "=r"(r[2]), "=r"(r[3]) : "r"(a));
}
__device__ __forceinline__ void ldm_x2(unsigned* r, unsigned a) {
    asm volatile("ldmatrix.sync.aligned.m8n8.x2.shared.b16 {%0,%1}, [%2];"
        : "=r"(r[0]), "=r"(r[1]) : "r"(a));
}
__device__ __forceinline__ void ldm_x2t(unsigned* r, unsigned a) {
    asm volatile("ldmatrix.sync.aligned.m8n8.x2.trans.shared.b16 {%0,%1}, [%2];"
        : "=r"(r[0]), "=r"(r[1]) : "r"(a));
}
__device__ __forceinline__ void mma16816(float* d, const unsigned* a, const unsigned* b) {
    asm volatile(
        "mma.sync.aligned.m16n8k16.row.col.f32.bf16.bf16.f32 "
        "{%0,%1,%2,%3}, {%4,%5,%6,%7}, {%8,%9}, {%0,%1,%2,%3};"
        : "+f"(d[0]), "+f"(d[1]), "+f"(d[2]), "+f"(d[3])
        : "r"(a[0]), "r"(a[1]), "r"(a[2]), "r"(a[3]), "r"(b[0]), "r"(b[1]));
}
__device__ __forceinline__ unsigned cvt_bf16x2(float lo, float hi) {
    unsigned r;
    asm("cvt.rn.bf16x2.f32 %0, %1, %2;" : "=r"(r) : "f"(hi), "f"(lo));  // d.hi=%1, d.lo=%2
    return r;
}

// ---------------- scratch (static device memory; no allocation) ----------------
__device__ float    g_sq[NATOMS];
__device__ float    g_s0[NATOMS];
__device__ int      g_cnt[NATOMS];
__device__ unsigned g_keys[NATOMS];
__device__ unsigned g_hist[NBINS];
__device__ unsigned g_chist[NCHUNK];   // coarse 64-bin-chunk histogram
__device__ int      g_H;
__device__ int      g_r;
__device__ int      g_m;
__device__ int      g_done;
__device__ ull      g_bbuf[NATOMS];
__device__ int      g_sel[NATOMS];
__device__ int      g_idx[NSEL];
__device__ __align__(16) __nv_bfloat16 g_qh[NSEL * HID];  // q * scale*log2e, hi part
__device__ __align__(16) __nv_bfloat16 g_ql[NSEL * HID];  // q residual
__device__ __align__(16) __nv_bfloat16 g_kh[NSEL * HID];  // k hi part
__device__ __align__(16) __nv_bfloat16 g_kl[NSEL * HID];  // k residual
__device__ __align__(16) __nv_bfloat16 g_vh[NSEL * HID];  // V hi part
__device__ __align__(16) __nv_bfloat16 g_vl[NSEL * HID];  // V residual
__device__ __align__(16) float g_av[NSEL * HID];
__device__ float    g_mav[HID];

// ---------------- 0: init (zero hist/chist/cnt + ligand center + per-atom base) ----------------
__global__ void k_init(const float* __restrict__ lig, const float* __restrict__ pos) {
    __shared__ float c3[3];
    int t = threadIdx.x;
    if (t < 32) {
        float x = lig[t * 3 + 0], y = lig[t * 3 + 1], z = lig[t * 3 + 2];
        #pragma unroll
        for (int o = 16; o > 0; o >>= 1) {
            x += __shfl_down_sync(0xFFFFFFFFu, x, o);
            y += __shfl_down_sync(0xFFFFFFFFu, y, o);
            z += __shfl_down_sync(0xFFFFFFFFu, z, o);
        }
        if (t == 0) {
            c3[0] = x * (1.0f / NLIG);
            c3[1] = y * (1.0f / NLIG);
            c3[2] = z * (1.0f / NLIG);
        }
    }
    __syncthreads();
    int gi = blockIdx.x * 256 + t;
    if (gi < NBINS) g_hist[gi] = 0;
    if (gi < NCHUNK) g_chist[gi] = 0;
    int ci = gi - NBINS;
    if (ci >= 0 && ci < NATOMS) g_cnt[ci] = 0;
    if (gi == 0) { g_m = 0; g_done = 0; }
    if (gi < NATOMS) {
        float x = pos[gi * 3 + 0], y = pos[gi * 3 + 1], z = pos[gi * 3 + 2];
        g_sq[gi] = fmaf(z, z, fmaf(y, y, x * x));
        float dx = x - c3[0], dy = y - c3[1], dz = z - c3[2];
        float d = sqrtf(fmaf(dz, dz, fmaf(dy, dy, dx * dx)));
        g_s0[gi] = 1.0f / (1.0f + d / 5.0f);
    }
}

// ---------------- 1: neighbor counting, FFMA2-packed (2 j-atoms per iter) ----------------
__global__ __launch_bounds__(256) void k_neighbor(const float* __restrict__ pos) {
    __shared__ ull sX[128], sY[128], sZ[128], sW[128];
    int tid = threadIdx.x;
    int i = blockIdx.x * 256 + tid;
    float px = pos[i * 3 + 0], py = pos[i * 3 + 1], pz = pos[i * 3 + 2];
    float ci = 4.5f - 0.5f * g_sq[i];
    ull px2 = f2_pack(px, px), py2 = f2_pack(py, py), pz2 = f2_pack(pz, pz);
    ull ci2 = f2_pack(ci, ci);
    float* fX = (float*)sX; float* fY = (float*)sY; float* fZ = (float*)sZ; float* fW = (float*)sW;
    int cnt = 0;
    int j0 = blockIdx.y * 2048;
    for (int jt = 0; jt < 8; jt++) {
        int j = j0 + jt * 256 + tid;
        fX[tid] = pos[j * 3 + 0];
        fY[tid] = pos[j * 3 + 1];
        fZ[tid] = pos[j * 3 + 2];
        fW[tid] = -0.5f * g_sq[j];
        __syncthreads();
        #pragma unroll 4
        for (int jp = 0; jp < 128; jp++) {
            ull base = f2_add(sW[jp], ci2);
            ull v = f2_fma(px2, sX[jp], f2_fma(py2, sY[jp], f2_fma(pz2, sZ[jp], base)));
            float vlo, vhi; f2_unpack(v, vlo, vhi);
            cnt += (vlo > 0.0f);
            cnt += (vhi > 0.0f);
        }
        __syncthreads();
    }
    atomicAdd(&g_cnt[i], cnt);
}

// ---------------- 2: final scores -> sortable keys + fine & coarse histograms ----------------
__global__ void k_scorekey() {
    int i = blockIdx.x * blockDim.x + threadIdx.x;
    if (i >= NATOMS) return;
    float surface = 1.0f / (float)g_cnt[i];
    float s = g_s0[i] + 0.5f * surface;
    unsigned key = __float_as_uint(s);
    g_keys[i] = key;
    atomicAdd(&g_hist[key >> 16], 1u);
    atomicAdd(&g_chist[key >> 22], 1u);   // 64-bin chunk
}

// ---------------- 3: threshold bin — parallel over chunk hist (no 64K serial stream) ----------------
__global__ __launch_bounds__(1024) void k_scan() {
    __shared__ unsigned csum[NCHUNK];
    __shared__ unsigned hs[64];
    __shared__ int s_chunk;
    __shared__ unsigned s_above;
    int t = threadIdx.x;
    csum[t] = g_chist[t];
    __syncthreads();
    // parallel suffix scan: csum[t] = sum of chunks t..1023
    for (int o = 1; o < NCHUNK; o <<= 1) {
        unsigned v = (t + o < NCHUNK) ? csum[t + o] : 0u;
        __syncthreads();
        csum[t] += v;
        __syncthreads();
    }
    // unique crossing: suffix(t) >= NSEL, suffix(t+1) < NSEL
    {
        unsigned mine = csum[t];
        unsigned nxt = (t + 1 < NCHUNK) ? csum[t + 1] : 0u;
        if (mine >= (unsigned)NSEL && nxt < (unsigned)NSEL) { s_chunk = t; s_above = nxt; }
    }
    __syncthreads();
    int chunk = s_chunk;
    unsigned above = s_above;
    if (t < 64) hs[t] = g_hist[chunk * 64 + t];
    __syncthreads();
    // suffix scan within the 64-bin chunk
    for (int o = 1; o < 64; o <<= 1) {
        unsigned v = (t < 64 && t + o < 64) ? hs[t + o] : 0u;
        __syncthreads();
        if (t < 64) hs[t] += v;
        __syncthreads();
    }
    if (t < 64) {
        unsigned mine = above + hs[t];
        unsigned nxt  = above + ((t + 1 < 64) ? hs[t + 1] : 0u);
        if (mine >= (unsigned)NSEL && nxt < (unsigned)NSEL) {
            g_H = chunk * 64 + t;
            g_r = (int)((unsigned)NSEL - nxt);
        }
    }
}

// ---------------- 4: boundary-bin elements ----------------
__global__ void k_boundary() {
    int i = blockIdx.x * blockDim.x + threadIdx.x;
    if (i >= NATOMS) return;
    unsigned key = g_keys[i];
    if ((int)(key >> 16) == g_H) {
        int p = atomicAdd(&g_m, 1);
        g_bbuf[p] = ((ull)key << 32) | (ull)(0xFFFFFFFFu - (unsigned)i);
    }
}

// ---------------- 5: selection flags ----------------
__global__ void k_flags() {
    int i = blockIdx.x * blockDim.x + threadIdx.x;
    if (i >= NATOMS) return;
    unsigned key = g_keys[i];
    int hi = (int)(key >> 16);
    int s = 0;
    if (hi > g_H) s = 1;
    else if (hi == g_H) {
        ull mine = ((ull)key << 32) | (ull)(0xFFFFFFFFu - (unsigned)i);
        int m = g_m, cnt = 0, r = g_r;
        for (int t = 0; t < m; t++) cnt += (g_bbuf[t] > mine);
        if (cnt < r) s = 1;
    }
    g_sel[i] = s;
}

// ---------------- 6: single-pass deterministic compaction ----------------
__global__ __launch_bounds__(256) void k_compact_all() {
    __shared__ int sc[256];
    __shared__ int s_off;
    int t = threadIdx.x, b = blockIdx.x;
    int pre = b * 256;
    int s = 0;
    for (int j = t; j < pre; j += 256) s += g_sel[j];
    sc[t] = s;
    __syncthreads();
    for (int o = 128; o > 0; o >>= 1) {
        if (t < o) sc[t] += sc[t + o];
        __syncthreads();
    }
    if (t == 0) s_off = sc[0];
    __syncthreads();
    int i = pre + t;
    int f = g_sel[i];
    sc[t] = f;
    __syncthreads();
    for (int o = 1; o < 256; o <<= 1) {
        int v = (t >= o) ? sc[t - o] : 0;
        __syncthreads();
        sc[t] += v;
        __syncthreads();
    }
    if (f) g_idx[s_off + sc[t] - 1] = i;
}

// ---------------- 7: gather + embed + QKV (16 rows/block; bf16 hi/lo outputs) ----------------
__global__ __launch_bounds__(256) void k_qkv(
    const float* __restrict__ x,
    const float* __restrict__ Wn, const float* __restrict__ bn,
    const float* __restrict__ Wq, const float* __restrict__ bq,
    const float* __restrict__ Wk, const float* __restrict__ bk,
    const float* __restrict__ Wv, const float* __restrict__ bv)
{
    __shared__ float hs[16][HID];
    int t = threadIdx.x;
    int c = t & 127;          // column
    int half = t >> 7;        // 0/1 -> rows 0-7 / 8-15
    int r0 = blockIdx.x * 16;
    #pragma unroll
    for (int k = 0; k < 8; k++) {
        int rr = half * 8 + k;
        int row = g_idx[r0 + rr];
        const float* xr = x + row * NODE_F;
        float acc = bn[c];
        #pragma unroll
        for (int f = 0; f < NODE_F; f++) acc = fmaf(__ldg(xr + f), Wn[f * HID + c], acc);
        hs[rr][c] = acc;
    }
    __syncthreads();
    float aq[8], ak[8], av[8];
    #pragma unroll
    for (int rr = 0; rr < 8; rr++) { aq[rr] = bq[c]; ak[rr] = bk[c]; av[rr] = bv[c]; }
    for (int d = 0; d < HID; d++) {
        float wq = Wq[d * HID + c], wk = Wk[d * HID + c], wv = Wv[d * HID + c];
        #pragma unroll
        for (int rr = 0; rr < 8; rr++) {
            float h = hs[half * 8 + rr][d];
            aq[rr] = fmaf(h, wq, aq[rr]);
            ak[rr] = fmaf(h, wk, ak[rr]);
            av[rr] = fmaf(h, wv, av[rr]);
        }
    }
    const float cs = 0.25f * 1.4426950408889634f;  // scale * log2(e), folded into Q
    #pragma unroll
    for (int rr = 0; rr < 8; rr++) {
        int o = (r0 + half * 8 + rr) * HID + c;
        float qs = aq[rr] * cs;
        __nv_bfloat16 qhi = __float2bfloat16(qs);
        g_qh[o] = qhi;
        g_ql[o] = __float2bfloat16(qs - __bfloat162float(qhi));
        float kf = ak[rr];
        __nv_bfloat16 khi = __float2bfloat16(kf);
        g_kh[o] = khi;
        g_kl[o] = __float2bfloat16(kf - __bfloat162float(khi));
        float vf = av[rr];
        __nv_bfloat16 vhi = __float2bfloat16(vf);
        g_vh[o] = vhi;
        g_vl[o] = __float2bfloat16(vf - __bfloat162float(vhi));
    }
}

// ---------------- 8: tensor-core attention (full hi/lo split — proven R7 numerics) ----------------
// S = Qhi·Khi + Qhi·Klo + Qlo·Khi (~fp32 logits); p = ex2(S);
// O = P·Vhi + P·Vlo. Both Q/K and V residuals are REQUIRED: dropping either
// leaves a query-independent systematic error that survives the mean pool
// (measured: 1.5e-3 both times). No max-subtraction: logits ~ N(0,1).
__global__ __launch_bounds__(128) void k_attn_tc() {
    __shared__ __align__(16) __nv_bfloat16 sKh[TK][KPAD];
    __shared__ __align__(16) __nv_bfloat16 sKl[TK][KPAD];
    __shared__ __align__(16) __nv_bfloat16 sVh[TK][KPAD];
    __shared__ __align__(16) __nv_bfloat16 sVl[TK][KPAD];

    int h    = blockIdx.y;
    int q0   = blockIdx.x * TQ;
    int tid  = threadIdx.x;
    int warp = tid >> 5;
    int lane = tid & 31;

    // stage Q tile (64 rows x 16 cols, hi+lo) into K buffers, ldmatrix to regs
    {
        int row = tid >> 1, half = tid & 1;
        const uint4* sh = (const uint4*)(g_qh + (q0 + row) * HID + h * DH + half * 8);
        const uint4* sl = (const uint4*)(g_ql + (q0 + row) * HID + h * DH + half * 8);
        *(uint4*)&sKh[row][half * 8] = *sh;
        *(uint4*)&sKl[row][half * 8] = *sl;
    }
    __syncthreads();
    unsigned a_hi[4], a_lo[4];
    {
        int mrow = warp * 16 + ((lane >> 3) & 1) * 8 + (lane & 7);
        unsigned coff = (lane >> 4) * 16;
        ldm_x4(a_hi, scvt(&sKh[mrow][0]) + coff);
        ldm_x4(a_lo, scvt(&sKl[mrow][0]) + coff);
    }
    __syncthreads();

    float o[8];
    #pragma unroll
    for (int i = 0; i < 8; i++) o[i] = 0.0f;
    float l0 = 0.0f, l1 = 0.0f;

    int brow8  = lane & 7;                            // QK B: 8 key rows, d halves
    unsigned bcoff = ((lane >> 3) & 1) * 16;
    int vrow16 = (lane & 7) + ((lane >> 3) & 1) * 8;  // PV B: 16 key rows

    for (int kt = 0; kt < NSEL / TK; kt++) {
        {
            int row = tid;  // 128 rows
            int src = (kt * TK + row) * HID + h * DH;
            const uint4* kh = (const uint4*)(g_kh + src);
            const uint4* kl = (const uint4*)(g_kl + src);
            const uint4* vh = (const uint4*)(g_vh + src);
            const uint4* vl = (const uint4*)(g_vl + src);
            *(uint4*)&sKh[row][0] = kh[0]; *(uint4*)&sKh[row][8] = kh[1];
            *(uint4*)&sKl[row][0] = kl[0]; *(uint4*)&sKl[row][8] = kl[1];
            *(uint4*)&sVh[row][0] = vh[0]; *(uint4*)&sVh[row][8] = vh[1];
            *(uint4*)&sVl[row][0] = vl[0]; *(uint4*)&sVl[row][8] = vl[1];
        }
        __syncthreads();

        #pragma unroll
        for (int g16 = 0; g16 < TK / 16; g16++) {
            float S[8];
            #pragma unroll
            for (int i = 0; i < 8; i++) S[i] = 0.0f;
            #pragma unroll
            for (int half8 = 0; half8 < 2; half8++) {
                int kb = g16 * 16 + half8 * 8 + brow8;
                unsigned bh[2], bl[2];
                ldm_x2(bh, scvt(&sKh[kb][0]) + bcoff);
                ldm_x2(bl, scvt(&sKl[kb][0]) + bcoff);
                float* Sd = S + half8 * 4;
                mma16816(Sd, a_hi, bh);
                mma16816(Sd, a_hi, bl);
                mma16816(Sd, a_lo, bh);
            }
            float p0 = ex2(S[0]), p1 = ex2(S[1]), p2 = ex2(S[2]), p3 = ex2(S[3]);
            float p4 = ex2(S[4]), p5 = ex2(S[5]), p6 = ex2(S[6]), p7 = ex2(S[7]);
            l0 += (p0 + p1) + (p4 + p5);   // D rows r0
            l1 += (p2 + p3) + (p6 + p7);   // D rows r0+8
            unsigned pa[4];
            pa[0] = cvt_bf16x2(p0, p1);
            pa[1] = cvt_bf16x2(p2, p3);
            pa[2] = cvt_bf16x2(p4, p5);
            pa[3] = cvt_bf16x2(p6, p7);
            int vr = g16 * 16 + vrow16;
            #pragma unroll
            for (int dh2 = 0; dh2 < 2; dh2++) {
                unsigned bvh[2], bvl[2];
                ldm_x2t(bvh, scvt(&sVh[vr][dh2 * 8]));
                ldm_x2t(bvl, scvt(&sVl[vr][dh2 * 8]));
                mma16816(o + dh2 * 4, pa, bvh);
                mma16816(o + dh2 * 4, pa, bvl);
            }
        }
        __syncthreads();
    }

    l0 += __shfl_xor_sync(0xFFFFFFFFu, l0, 1);
    l0 += __shfl_xor_sync(0xFFFFFFFFu, l0, 2);
    l1 += __shfl_xor_sync(0xFFFFFFFFu, l1, 1);
    l1 += __shfl_xor_sync(0xFFFFFFFFu, l1, 2);
    float inv0 = 1.0f / l0, inv1 = 1.0f / l1;

    int r0c = lane >> 2;
    int cc  = (lane & 3) * 2;
    int row0 = q0 + warp * 16 + r0c;
    int row1 = row0 + 8;
    float* d0 = g_av + row0 * HID + h * DH;
    float* d1 = g_av + row1 * HID + h * DH;
    d0[cc]     = o[0] * inv0;  d0[cc + 1] = o[1] * inv0;
    d1[cc]     = o[2] * inv1;  d1[cc + 1] = o[3] * inv1;
    d0[cc + 8] = o[4] * inv0;  d0[cc + 9] = o[5] * inv0;
    d1[cc + 8] = o[6] * inv1;  d1[cc + 9] = o[7] * inv1;
}

// ---------------- 9: column mean + (last block) Wo/MLP head ----------------
__global__ __launch_bounds__(256) void k_colsum_final(
    const float* __restrict__ Wo, const float* __restrict__ bo,
    const float* __restrict__ W1, const float* __restrict__ b1,
    const float* __restrict__ W2, const float* __restrict__ b2,
    float* __restrict__ out)
{
    __shared__ float sm[256];
    __shared__ int is_last;
    int col = blockIdx.x;
    int t = threadIdx.x;
    float s = 0.0f;
    for (int r = t; r < NSEL; r += 256) s += g_av[r * HID + col];
    sm[t] = s;
    __syncthreads();
    for (int o = 128; o > 0; o >>= 1) {
        if (t < o) sm[t] += sm[t + o];
        __syncthreads();
    }
    if (t == 0) {
        g_mav[col] = sm[0] * (1.0f / NSEL);
        __threadfence();
        is_last = (atomicAdd(&g_done, 1) == HID - 1);
    }
    __syncthreads();
    if (!is_last) return;

    __shared__ float mav[HID];
    __shared__ float pooled[HID];
    __shared__ float t1[OUTD];
    if (t < HID) mav[t] = g_mav[t];
    __syncthreads();
    if (t < HID) {
        float acc = bo[t];
        for (int d = 0; d < HID; d++) acc = fmaf(mav[d], Wo[d * HID + t], acc);
        pooled[t] = acc;
    }
    __syncthreads();
    {
        float acc = b1[t];
        for (int d = 0; d < HID; d++) acc = fmaf(pooled[d], W1[d * OUTD + t], acc);
        t1[t] = fmaxf(acc, 0.0f);
    }
    __syncthreads();
    {
        float acc = b2[t];
        for (int d = 0; d < OUTD; d++) acc = fmaf(t1[d], W2[d * OUTD + t], acc);
        out[t] = acc;
    }
}

// ---------------- launcher ----------------
extern "C" void kernel_launch(void* const* d_in, const int* in_sizes, int n_in,
                              void* d_out, int out_size)
{
    const float* x    = (const float*)d_in[0];
    const float* pos  = (const float*)d_in[1];
    const float* lig  = (const float*)d_in[2];
    const float* Wn   = (const float*)d_in[3];
    const float* bn   = (const float*)d_in[4];
    const float* Wq   = (const float*)d_in[5];
    const float* bq   = (const float*)d_in[6];
    const float* Wk   = (const float*)d_in[7];
    const float* bk   = (const float*)d_in[8];
    const float* Wv   = (const float*)d_in[9];
    const float* bv   = (const float*)d_in[10];
    const float* Wo   = (const float*)d_in[11];
    const float* bo   = (const float*)d_in[12];
    const float* W1   = (const float*)d_in[13];
    const float* b1   = (const float*)d_in[14];
    const float* W2   = (const float*)d_in[15];
    const float* b2   = (const float*)d_in[16];
    float* out = (float*)d_out;

    k_init<<<(NBINS + NATOMS) / 256, 256>>>(lig, pos);
    k_neighbor<<<dim3(NATOMS / 256, 8), 256>>>(pos);
    k_scorekey<<<NATOMS / 256, 256>>>();
    k_scan<<<1, 1024>>>();
    k_boundary<<<NATOMS / 256, 256>>>();
    k_flags<<<NATOMS / 256, 256>>>();
    k_compact_all<<<64, 256>>>();
    k_qkv<<<NSEL / 16, 256>>>(x, Wn, bn, Wq, bq, Wk, bk, Wv, bv);
    k_attn_tc<<<dim3(NSEL / TQ, HEADS), 128>>>();
    k_colsum_final<<<HID, 256>>>(Wo, bo, W1, b1, W2, b2, out);
}

// round 11
// speedup vs baseline: 1.1328x; 1.0161x over previous
#include <cuda_runtime.h>
#include <cuda_bf16.h>
#include <stdint.h>

// ---------------- problem constants ----------------
#define NATOMS   16384
#define NSEL     4096
#define NODE_F   8
#define HID      128
#define HEADS    8
#define DH       16
#define OUTD     256
#define NLIG     32
#define NBINS    65536
#define NCHUNK   1024     // coarse chunks of 64 fine bins

#define TQ 64      // queries per attention block (16 per warp-quad)
#define TK 128     // keys per smem tile
#define KPAD 24    // smem row stride in bf16 (48B: 16B-aligned, ldmatrix conflict-free)
#define TILEB (TK * KPAD * 2)   // 6144 bytes per tile array

typedef unsigned long long ull;

// ---------------- packed f32x2 helpers (Blackwell FFMA2 path) ----------------
__device__ __forceinline__ ull f2_pack(float lo, float hi) {
    ull r; asm("mov.b64 %0, {%1, %2};" : "=l"(r) : "f"(lo), "f"(hi)); return r;
}
__device__ __forceinline__ void f2_unpack(ull v, float& lo, float& hi) {
    asm("mov.b64 {%0, %1}, %2;" : "=f"(lo), "=f"(hi) : "l"(v));
}
__device__ __forceinline__ ull f2_add(ull a, ull b) {
    ull r; asm("add.rn.f32x2 %0, %1, %2;" : "=l"(r) : "l"(a), "l"(b)); return r;
}
__device__ __forceinline__ ull f2_fma(ull a, ull b, ull c) {
    ull r; asm("fma.rn.f32x2 %0, %1, %2, %3;" : "=l"(r) : "l"(a), "l"(b), "l"(c)); return r;
}
__device__ __forceinline__ float ex2(float x) {
    float r; asm("ex2.approx.f32 %0, %1;" : "=f"(r) : "f"(x)); return r;
}

// ---------------- tensor-core helpers ----------------
__device__ __forceinline__ unsigned scvt(const void* p) {
    return (unsigned)__cvta_generic_to_shared(p);
}
__device__ __forceinline__ void ldm_x4(unsigned* r, unsigned a) {
    asm volatile("ldmatrix.sync.aligned.m8n8.x4.shared.b16 {%0,%1,%2,%3}, [%4];"
        : "=r"(r[0]), "=r"(r[1]), "=r"(r[2]), "=r"(r[3]) : "r"(a));
}
__device__ __forceinline__ void ldm_x2(unsigned* r, unsigned a) {
    asm volatile("ldmatrix.sync.aligned.m8n8.x2.shared.b16 {%0,%1}, [%2];"
        : "=r"(r[0]), "=r"(r[1]) : "r"(a));
}
__device__ __forceinline__ void ldm_x2t(unsigned* r, unsigned a) {
    asm volatile("ldmatrix.sync.aligned.m8n8.x2.trans.shared.b16 {%0,%1}, [%2];"
        : "=r"(r[0]), "=r"(r[1]) : "r"(a));
}
__device__ __forceinline__ void mma16816(float* d, const unsigned* a, const unsigned* b) {
    asm volatile(
        "mma.sync.aligned.m16n8k16.row.col.f32.bf16.bf16.f32 "
        "{%0,%1,%2,%3}, {%4,%5,%6,%7}, {%8,%9}, {%0,%1,%2,%3};"
        : "+f"(d[0]), "+f"(d[1]), "+f"(d[2]), "+f"(d[3])
        : "r"(a[0]), "r"(a[1]), "r"(a[2]), "r"(a[3]), "r"(b[0]), "r"(b[1]));
}
__device__ __forceinline__ unsigned cvt_bf16x2(float lo, float hi) {
    unsigned r;
    asm("cvt.rn.bf16x2.f32 %0, %1, %2;" : "=r"(r) : "f"(hi), "f"(lo));  // d.hi=%1, d.lo=%2
    return r;
}
// named barrier over 128 threads (one split-K half)
__device__ __forceinline__ void half_bar(int id) {
    asm volatile("bar.sync %0, %1;" :: "r"(id), "r"(128) : "memory");
}

// ---------------- scratch (static device memory; no allocation) ----------------
__device__ float    g_sq[NATOMS];
__device__ float    g_s0[NATOMS];
__device__ int      g_cnt[NATOMS];
__device__ unsigned g_keys[NATOMS];
__device__ unsigned g_hist[NBINS];
__device__ unsigned g_chist[NCHUNK];   // coarse 64-bin-chunk histogram
__device__ int      g_H;
__device__ int      g_r;
__device__ int      g_m;
__device__ int      g_done;
__device__ ull      g_bbuf[NATOMS];
__device__ int      g_sel[NATOMS];
__device__ int      g_idx[NSEL];
__device__ __align__(16) __nv_bfloat16 g_qh[NSEL * HID];  // q * scale*log2e, hi part
__device__ __align__(16) __nv_bfloat16 g_ql[NSEL * HID];  // q residual
__device__ __align__(16) __nv_bfloat16 g_kh[NSEL * HID];  // k hi part
__device__ __align__(16) __nv_bfloat16 g_kl[NSEL * HID];  // k residual
__device__ __align__(16) __nv_bfloat16 g_vh[NSEL * HID];  // V hi part
__device__ __align__(16) __nv_bfloat16 g_vl[NSEL * HID];  // V residual
__device__ __align__(16) float g_av[NSEL * HID];
__device__ float    g_mav[HID];

// ---------------- 0: init (zero hist/chist/cnt + ligand center + per-atom base) ----------------
__global__ void k_init(const float* __restrict__ lig, const float* __restrict__ pos) {
    __shared__ float c3[3];
    int t = threadIdx.x;
    if (t < 32) {
        float x = lig[t * 3 + 0], y = lig[t * 3 + 1], z = lig[t * 3 + 2];
        #pragma unroll
        for (int o = 16; o > 0; o >>= 1) {
            x += __shfl_down_sync(0xFFFFFFFFu, x, o);
            y += __shfl_down_sync(0xFFFFFFFFu, y, o);
            z += __shfl_down_sync(0xFFFFFFFFu, z, o);
        }
        if (t == 0) {
            c3[0] = x * (1.0f / NLIG);
            c3[1] = y * (1.0f / NLIG);
            c3[2] = z * (1.0f / NLIG);
        }
    }
    __syncthreads();
    int gi = blockIdx.x * 256 + t;
    if (gi < NBINS) g_hist[gi] = 0;
    if (gi < NCHUNK) g_chist[gi] = 0;
    int ci = gi - NBINS;
    if (ci >= 0 && ci < NATOMS) g_cnt[ci] = 0;
    if (gi == 0) { g_m = 0; g_done = 0; }
    if (gi < NATOMS) {
        float x = pos[gi * 3 + 0], y = pos[gi * 3 + 1], z = pos[gi * 3 + 2];
        g_sq[gi] = fmaf(z, z, fmaf(y, y, x * x));
        float dx = x - c3[0], dy = y - c3[1], dz = z - c3[2];
        float d = sqrtf(fmaf(dz, dz, fmaf(dy, dy, dx * dx)));
        g_s0[gi] = 1.0f / (1.0f + d / 5.0f);
    }
}

// ---------------- 1: neighbor counting, FFMA2-packed (2 j-atoms per iter) ----------------
__global__ __launch_bounds__(256) void k_neighbor(const float* __restrict__ pos) {
    __shared__ ull sX[128], sY[128], sZ[128], sW[128];
    int tid = threadIdx.x;
    int i = blockIdx.x * 256 + tid;
    float px = pos[i * 3 + 0], py = pos[i * 3 + 1], pz = pos[i * 3 + 2];
    float ci = 4.5f - 0.5f * g_sq[i];
    ull px2 = f2_pack(px, px), py2 = f2_pack(py, py), pz2 = f2_pack(pz, pz);
    ull ci2 = f2_pack(ci, ci);
    float* fX = (float*)sX; float* fY = (float*)sY; float* fZ = (float*)sZ; float* fW = (float*)sW;
    int cnt = 0;
    int j0 = blockIdx.y * 2048;
    for (int jt = 0; jt < 8; jt++) {
        int j = j0 + jt * 256 + tid;
        fX[tid] = pos[j * 3 + 0];
        fY[tid] = pos[j * 3 + 1];
        fZ[tid] = pos[j * 3 + 2];
        fW[tid] = -0.5f * g_sq[j];
        __syncthreads();
        #pragma unroll 4
        for (int jp = 0; jp < 128; jp++) {
            ull base = f2_add(sW[jp], ci2);
            ull v = f2_fma(px2, sX[jp], f2_fma(py2, sY[jp], f2_fma(pz2, sZ[jp], base)));
            float vlo, vhi; f2_unpack(v, vlo, vhi);
            cnt += (vlo > 0.0f);
            cnt += (vhi > 0.0f);
        }
        __syncthreads();
    }
    atomicAdd(&g_cnt[i], cnt);
}

// ---------------- 2: final scores -> sortable keys + fine & coarse histograms ----------------
__global__ void k_scorekey() {
    int i = blockIdx.x * blockDim.x + threadIdx.x;
    if (i >= NATOMS) return;
    float surface = 1.0f / (float)g_cnt[i];
    float s = g_s0[i] + 0.5f * surface;
    unsigned key = __float_as_uint(s);
    g_keys[i] = key;
    atomicAdd(&g_hist[key >> 16], 1u);
    atomicAdd(&g_chist[key >> 22], 1u);   // 64-bin chunk
}

// ---------------- 3: threshold bin — parallel over chunk hist ----------------
__global__ __launch_bounds__(1024) void k_scan() {
    __shared__ unsigned csum[NCHUNK];
    __shared__ unsigned hs[64];
    __shared__ int s_chunk;
    __shared__ unsigned s_above;
    int t = threadIdx.x;
    csum[t] = g_chist[t];
    __syncthreads();
    for (int o = 1; o < NCHUNK; o <<= 1) {
        unsigned v = (t + o < NCHUNK) ? csum[t + o] : 0u;
        __syncthreads();
        csum[t] += v;
        __syncthreads();
    }
    {
        unsigned mine = csum[t];
        unsigned nxt = (t + 1 < NCHUNK) ? csum[t + 1] : 0u;
        if (mine >= (unsigned)NSEL && nxt < (unsigned)NSEL) { s_chunk = t; s_above = nxt; }
    }
    __syncthreads();
    int chunk = s_chunk;
    unsigned above = s_above;
    if (t < 64) hs[t] = g_hist[chunk * 64 + t];
    __syncthreads();
    for (int o = 1; o < 64; o <<= 1) {
        unsigned v = (t < 64 && t + o < 64) ? hs[t + o] : 0u;
        __syncthreads();
        if (t < 64) hs[t] += v;
        __syncthreads();
    }
    if (t < 64) {
        unsigned mine = above + hs[t];
        unsigned nxt  = above + ((t + 1 < 64) ? hs[t + 1] : 0u);
        if (mine >= (unsigned)NSEL && nxt < (unsigned)NSEL) {
            g_H = chunk * 64 + t;
            g_r = (int)((unsigned)NSEL - nxt);
        }
    }
}

// ---------------- 4: boundary-bin elements ----------------
__global__ void k_boundary() {
    int i = blockIdx.x * blockDim.x + threadIdx.x;
    if (i >= NATOMS) return;
    unsigned key = g_keys[i];
    if ((int)(key >> 16) == g_H) {
        int p = atomicAdd(&g_m, 1);
        g_bbuf[p] = ((ull)key << 32) | (ull)(0xFFFFFFFFu - (unsigned)i);
    }
}

// ---------------- 5: selection flags ----------------
__global__ void k_flags() {
    int i = blockIdx.x * blockDim.x + threadIdx.x;
    if (i >= NATOMS) return;
    unsigned key = g_keys[i];
    int hi = (int)(key >> 16);
    int s = 0;
    if (hi > g_H) s = 1;
    else if (hi == g_H) {
        ull mine = ((ull)key << 32) | (ull)(0xFFFFFFFFu - (unsigned)i);
        int m = g_m, cnt = 0, r = g_r;
        for (int t = 0; t < m; t++) cnt += (g_bbuf[t] > mine);
        if (cnt < r) s = 1;
    }
    g_sel[i] = s;
}

// ---------------- 6: single-pass deterministic compaction ----------------
__global__ __launch_bounds__(256) void k_compact_all() {
    __shared__ int sc[256];
    __shared__ int s_off;
    int t = threadIdx.x, b = blockIdx.x;
    int pre = b * 256;
    int s = 0;
    for (int j = t; j < pre; j += 256) s += g_sel[j];
    sc[t] = s;
    __syncthreads();
    for (int o = 128; o > 0; o >>= 1) {
        if (t < o) sc[t] += sc[t + o];
        __syncthreads();
    }
    if (t == 0) s_off = sc[0];
    __syncthreads();
    int i = pre + t;
    int f = g_sel[i];
    sc[t] = f;
    __syncthreads();
    for (int o = 1; o < 256; o <<= 1) {
        int v = (t >= o) ? sc[t - o] : 0;
        __syncthreads();
        sc[t] += v;
        __syncthreads();
    }
    if (f) g_idx[s_off + sc[t] - 1] = i;
}

// ---------------- 7: gather + embed + QKV (16 rows/block; bf16 hi/lo outputs) ----------------
__global__ __launch_bounds__(256) void k_qkv(
    const float* __restrict__ x,
    const float* __restrict__ Wn, const float* __restrict__ bn,
    const float* __restrict__ Wq, const float* __restrict__ bq,
    const float* __restrict__ Wk, const float* __restrict__ bk,
    const float* __restrict__ Wv, const float* __restrict__ bv)
{
    __shared__ float hs[16][HID];
    int t = threadIdx.x;
    int c = t & 127;          // column
    int half = t >> 7;        // 0/1 -> rows 0-7 / 8-15
    int r0 = blockIdx.x * 16;
    #pragma unroll
    for (int k = 0; k < 8; k++) {
        int rr = half * 8 + k;
        int row = g_idx[r0 + rr];
        const float* xr = x + row * NODE_F;
        float acc = bn[c];
        #pragma unroll
        for (int f = 0; f < NODE_F; f++) acc = fmaf(__ldg(xr + f), Wn[f * HID + c], acc);
        hs[rr][c] = acc;
    }
    __syncthreads();
    float aq[8], ak[8], av[8];
    #pragma unroll
    for (int rr = 0; rr < 8; rr++) { aq[rr] = bq[c]; ak[rr] = bk[c]; av[rr] = bv[c]; }
    for (int d = 0; d < HID; d++) {
        float wq = Wq[d * HID + c], wk = Wk[d * HID + c], wv = Wv[d * HID + c];
        #pragma unroll
        for (int rr = 0; rr < 8; rr++) {
            float h = hs[half * 8 + rr][d];
            aq[rr] = fmaf(h, wq, aq[rr]);
            ak[rr] = fmaf(h, wk, ak[rr]);
            av[rr] = fmaf(h, wv, av[rr]);
        }
    }
    const float cs = 0.25f * 1.4426950408889634f;  // scale * log2(e), folded into Q
    #pragma unroll
    for (int rr = 0; rr < 8; rr++) {
        int o = (r0 + half * 8 + rr) * HID + c;
        float qs = aq[rr] * cs;
        __nv_bfloat16 qhi = __float2bfloat16(qs);
        g_qh[o] = qhi;
        g_ql[o] = __float2bfloat16(qs - __bfloat162float(qhi));
        float kf = ak[rr];
        __nv_bfloat16 khi = __float2bfloat16(kf);
        g_kh[o] = khi;
        g_kl[o] = __float2bfloat16(kf - __bfloat162float(khi));
        float vf = av[rr];
        __nv_bfloat16 vhi = __float2bfloat16(vf);
        g_vh[o] = vhi;
        g_vl[o] = __float2bfloat16(vf - __bfloat162float(vhi));
    }
}

// ---------------- 8: tensor-core attention, intra-block split-K x2 ----------------
// Numerics identical to the proven R7/R10 scheme (Q/K/V all hi/lo split).
// 256 threads: warps 0-3 process K tiles 0-15, warps 4-7 tiles 16-31 for the
// SAME 64 queries, each half in its own 24KB smem tile set with its own named
// barrier. Partial (o, l) combined via smem at the end (sums add linearly; no
// max-subtraction needed: logits ~ N(0,1)). Doubles warps/SMSP to hide
// MUFU/ldmatrix latency (R10: 21% issue utilization on this kernel's floor).
__global__ __launch_bounds__(256) void k_attn_tc() {
    __shared__ __align__(16) char sraw[8 * TILEB];   // exactly 48KB

    int h    = blockIdx.y;
    int q0   = blockIdx.x * TQ;
    int tid  = threadIdx.x;
    int warp = tid >> 5;
    int lane = tid & 31;
    int qw   = warp & 3;      // query sub-tile (16 rows)
    int half = warp >> 2;     // split-K half
    int lt   = tid & 127;     // thread index within half

    __nv_bfloat16 (*sKh)[KPAD] = (__nv_bfloat16 (*)[KPAD])(sraw + half * 4 * TILEB + 0 * TILEB);
    __nv_bfloat16 (*sKl)[KPAD] = (__nv_bfloat16 (*)[KPAD])(sraw + half * 4 * TILEB + 1 * TILEB);
    __nv_bfloat16 (*sVh)[KPAD] = (__nv_bfloat16 (*)[KPAD])(sraw + half * 4 * TILEB + 2 * TILEB);
    __nv_bfloat16 (*sVl)[KPAD] = (__nv_bfloat16 (*)[KPAD])(sraw + half * 4 * TILEB + 3 * TILEB);

    // ---- stage Q tile (64 rows x 16 cols, hi+lo) into half-0 K buffers ----
    {
        __nv_bfloat16 (*qH)[KPAD] = (__nv_bfloat16 (*)[KPAD])(sraw);
        __nv_bfloat16 (*qL)[KPAD] = (__nv_bfloat16 (*)[KPAD])(sraw + TILEB);
        if (tid < 128) {
            int row = tid >> 1, hf = tid & 1;
            *(uint4*)&qH[row][hf * 8] = *(const uint4*)(g_qh + (q0 + row) * HID + h * DH + hf * 8);
            *(uint4*)&qL[row][hf * 8] = *(const uint4*)(g_ql + (q0 + row) * HID + h * DH + hf * 8);
        }
        __syncthreads();
    }
    unsigned a_hi[4], a_lo[4];
    {
        __nv_bfloat16 (*qH)[KPAD] = (__nv_bfloat16 (*)[KPAD])(sraw);
        __nv_bfloat16 (*qL)[KPAD] = (__nv_bfloat16 (*)[KPAD])(sraw + TILEB);
        int mrow = qw * 16 + ((lane >> 3) & 1) * 8 + (lane & 7);
        unsigned coff = (lane >> 4) * 16;
        ldm_x4(a_hi, scvt(&qH[mrow][0]) + coff);
        ldm_x4(a_lo, scvt(&qL[mrow][0]) + coff);
    }
    __syncthreads();

    float o[8];
    #pragma unroll
    for (int i = 0; i < 8; i++) o[i] = 0.0f;
    float l0 = 0.0f, l1 = 0.0f;

    int brow8  = lane & 7;                            // QK B: 8 key rows, d halves
    unsigned bcoff = ((lane >> 3) & 1) * 16;
    int vrow16 = (lane & 7) + ((lane >> 3) & 1) * 8;  // PV B: 16 key rows
    int bar_id = 1 + half;

    for (int it = 0; it < 16; it++) {
        int kt = half * 16 + it;
        {
            int src = (kt * TK + lt) * HID + h * DH;
            const uint4* kh = (const uint4*)(g_kh + src);
            const uint4* kl = (const uint4*)(g_kl + src);
            const uint4* vh = (const uint4*)(g_vh + src);
            const uint4* vl = (const uint4*)(g_vl + src);
            *(uint4*)&sKh[lt][0] = kh[0]; *(uint4*)&sKh[lt][8] = kh[1];
            *(uint4*)&sKl[lt][0] = kl[0]; *(uint4*)&sKl[lt][8] = kl[1];
            *(uint4*)&sVh[lt][0] = vh[0]; *(uint4*)&sVh[lt][8] = vh[1];
            *(uint4*)&sVl[lt][0] = vl[0]; *(uint4*)&sVl[lt][8] = vl[1];
        }
        half_bar(bar_id);

        #pragma unroll
        for (int g16 = 0; g16 < TK / 16; g16++) {
            float S[8];
            #pragma unroll
            for (int i = 0; i < 8; i++) S[i] = 0.0f;
            #pragma unroll
            for (int half8 = 0; half8 < 2; half8++) {
                int kb = g16 * 16 + half8 * 8 + brow8;
                unsigned bh[2], bl[2];
                ldm_x2(bh, scvt(&sKh[kb][0]) + bcoff);
                ldm_x2(bl, scvt(&sKl[kb][0]) + bcoff);
                float* Sd = S + half8 * 4;
                mma16816(Sd, a_hi, bh);
                mma16816(Sd, a_hi, bl);
                mma16816(Sd, a_lo, bh);
            }
            float p0 = ex2(S[0]), p1 = ex2(S[1]), p2 = ex2(S[2]), p3 = ex2(S[3]);
            float p4 = ex2(S[4]), p5 = ex2(S[5]), p6 = ex2(S[6]), p7 = ex2(S[7]);
            l0 += (p0 + p1) + (p4 + p5);   // D rows r0
            l1 += (p2 + p3) + (p6 + p7);   // D rows r0+8
            unsigned pa[4];
            pa[0] = cvt_bf16x2(p0, p1);
            pa[1] = cvt_bf16x2(p2, p3);
            pa[2] = cvt_bf16x2(p4, p5);
            pa[3] = cvt_bf16x2(p6, p7);
            int vr = g16 * 16 + vrow16;
            #pragma unroll
            for (int dh2 = 0; dh2 < 2; dh2++) {
                unsigned bvh[2], bvl[2];
                ldm_x2t(bvh, scvt(&sVh[vr][dh2 * 8]));
                ldm_x2t(bvl, scvt(&sVl[vr][dh2 * 8]));
                mma16816(o + dh2 * 4, pa, bvh);
                mma16816(o + dh2 * 4, pa, bvl);
            }
        }
        half_bar(bar_id);
    }

    // ---- combine the two K-halves (smem overlay on dead tile buffers) ----
    __syncthreads();
    float* sO = (float*)sraw;   // 4*32*10 floats = 5KB << 48KB
    if (half == 1) {
        float* dst = sO + (qw * 32 + lane) * 10;
        #pragma unroll
        for (int i = 0; i < 8; i++) dst[i] = o[i];
        dst[8] = l0; dst[9] = l1;
    }
    __syncthreads();
    if (half == 1) return;

    {
        const float* srcp = sO + (qw * 32 + lane) * 10;
        #pragma unroll
        for (int i = 0; i < 8; i++) o[i] += srcp[i];
        l0 += srcp[8]; l1 += srcp[9];
    }
    l0 += __shfl_xor_sync(0xFFFFFFFFu, l0, 1);
    l0 += __shfl_xor_sync(0xFFFFFFFFu, l0, 2);
    l1 += __shfl_xor_sync(0xFFFFFFFFu, l1, 1);
    l1 += __shfl_xor_sync(0xFFFFFFFFu, l1, 2);
    float inv0 = 1.0f / l0, inv1 = 1.0f / l1;

    int r0c = lane >> 2;
    int cc  = (lane & 3) * 2;
    int row0 = q0 + qw * 16 + r0c;
    int row1 = row0 + 8;
    float* d0 = g_av + row0 * HID + h * DH;
    float* d1 = g_av + row1 * HID + h * DH;
    d0[cc]     = o[0] * inv0;  d0[cc + 1] = o[1] * inv0;
    d1[cc]     = o[2] * inv1;  d1[cc + 1] = o[3] * inv1;
    d0[cc + 8] = o[4] * inv0;  d0[cc + 9] = o[5] * inv0;
    d1[cc + 8] = o[6] * inv1;  d1[cc + 9] = o[7] * inv1;
}

// ---------------- 9: column mean + (last block) Wo/MLP head ----------------
__global__ __launch_bounds__(256) void k_colsum_final(
    const float* __restrict__ Wo, const float* __restrict__ bo,
    const float* __restrict__ W1, const float* __restrict__ b1,
    const float* __restrict__ W2, const float* __restrict__ b2,
    float* __restrict__ out)
{
    __shared__ float sm[256];
    __shared__ int is_last;
    int col = blockIdx.x;
    int t = threadIdx.x;
    float s = 0.0f;
    for (int r = t; r < NSEL; r += 256) s += g_av[r * HID + col];
    sm[t] = s;
    __syncthreads();
    for (int o = 128; o > 0; o >>= 1) {
        if (t < o) sm[t] += sm[t + o];
        __syncthreads();
    }
    if (t == 0) {
        g_mav[col] = sm[0] * (1.0f / NSEL);
        __threadfence();
        is_last = (atomicAdd(&g_done, 1) == HID - 1);
    }
    __syncthreads();
    if (!is_last) return;

    __shared__ float mav[HID];
    __shared__ float pooled[HID];
    __shared__ float t1[OUTD];
    if (t < HID) mav[t] = g_mav[t];
    __syncthreads();
    if (t < HID) {
        float acc = bo[t];
        for (int d = 0; d < HID; d++) acc = fmaf(mav[d], Wo[d * HID + t], acc);
        pooled[t] = acc;
    }
    __syncthreads();
    {
        float acc = b1[t];
        for (int d = 0; d < HID; d++) acc = fmaf(pooled[d], W1[d * OUTD + t], acc);
        t1[t] = fmaxf(acc, 0.0f);
    }
    __syncthreads();
    {
        float acc = b2[t];
        for (int d = 0; d < OUTD; d++) acc = fmaf(t1[d], W2[d * OUTD + t], acc);
        out[t] = acc;
    }
}

// ---------------- launcher ----------------
extern "C" void kernel_launch(void* const* d_in, const int* in_sizes, int n_in,
                              void* d_out, int out_size)
{
    const float* x    = (const float*)d_in[0];
    const float* pos  = (const float*)d_in[1];
    const float* lig  = (const float*)d_in[2];
    const float* Wn   = (const float*)d_in[3];
    const float* bn   = (const float*)d_in[4];
    const float* Wq   = (const float*)d_in[5];
    const float* bq   = (const float*)d_in[6];
    const float* Wk   = (const float*)d_in[7];
    const float* bk   = (const float*)d_in[8];
    const float* Wv   = (const float*)d_in[9];
    const float* bv   = (const float*)d_in[10];
    const float* Wo   = (const float*)d_in[11];
    const float* bo   = (const float*)d_in[12];
    const float* W1   = (const float*)d_in[13];
    const float* b1   = (const float*)d_in[14];
    const float* W2   = (const float*)d_in[15];
    const float* b2   = (const float*)d_in[16];
    float* out = (float*)d_out;

    k_init<<<(NBINS + NATOMS) / 256, 256>>>(lig, pos);
    k_neighbor<<<dim3(NATOMS / 256, 8), 256>>>(pos);
    k_scorekey<<<NATOMS / 256, 256>>>();
    k_scan<<<1, 1024>>>();
    k_boundary<<<NATOMS / 256, 256>>>();
    k_flags<<<NATOMS / 256, 256>>>();
    k_compact_all<<<64, 256>>>();
    k_qkv<<<NSEL / 16, 256>>>(x, Wn, bn, Wq, bq, Wk, bk, Wv, bv);
    k_attn_tc<<<dim3(NSEL / TQ, HEADS), 256>>>();
    k_colsum_final<<<HID, 256>>>(Wo, bo, W1, b1, W2, b2, out);
}

// round 12
// speedup vs baseline: 1.3981x; 1.2342x over previous
#include <cuda_runtime.h>
#include <cuda_bf16.h>
#include <stdint.h>

// ---------------- problem constants ----------------
#define NATOMS   16384
#define NSEL     4096
#define NODE_F   8
#define HID      128
#define HEADS    8
#define DH       16
#define OUTD     256
#define NLIG     32
#define NBINS    65536
#define NCHUNK   1024     // coarse chunks of 64 fine bins
#define CDIM     48       // spatial cells per axis (cell size 3.0)
#define NCELLS   (CDIM * CDIM * CDIM)   // 110592
#define CBLK     (NCELLS / 256)         // 432 blocks over cells

#define TQ 64      // queries per attention block (16 per warp-quad)
#define TK 128     // keys per smem tile
#define KPAD 24    // smem row stride in bf16 (48B: 16B-aligned, ldmatrix conflict-free)
#define TILEB (TK * KPAD * 2)   // 6144 bytes per tile array

typedef unsigned long long ull;

// ---------------- helpers ----------------
__device__ __forceinline__ float ex2(float x) {
    float r; asm("ex2.approx.f32 %0, %1;" : "=f"(r) : "f"(x)); return r;
}
__device__ __forceinline__ unsigned scvt(const void* p) {
    return (unsigned)__cvta_generic_to_shared(p);
}
__device__ __forceinline__ void ldm_x4(unsigned* r, unsigned a) {
    asm volatile("ldmatrix.sync.aligned.m8n8.x4.shared.b16 {%0,%1,%2,%3}, [%4];"
        : "=r"(r[0]), "=r"(r[1]), "=r"(r[2]), "=r"(r[3]) : "r"(a));
}
__device__ __forceinline__ void ldm_x2(unsigned* r, unsigned a) {
    asm volatile("ldmatrix.sync.aligned.m8n8.x2.shared.b16 {%0,%1}, [%2];"
        : "=r"(r[0]), "=r"(r[1]) : "r"(a));
}
__device__ __forceinline__ void ldm_x2t(unsigned* r, unsigned a) {
    asm volatile("ldmatrix.sync.aligned.m8n8.x2.trans.shared.b16 {%0,%1}, [%2];"
        : "=r"(r[0]), "=r"(r[1]) : "r"(a));
}
__device__ __forceinline__ void mma16816(float* d, const unsigned* a, const unsigned* b) {
    asm volatile(
        "mma.sync.aligned.m16n8k16.row.col.f32.bf16.bf16.f32 "
        "{%0,%1,%2,%3}, {%4,%5,%6,%7}, {%8,%9}, {%0,%1,%2,%3};"
        : "+f"(d[0]), "+f"(d[1]), "+f"(d[2]), "+f"(d[3])
        : "r"(a[0]), "r"(a[1]), "r"(a[2]), "r"(a[3]), "r"(b[0]), "r"(b[1]));
}
__device__ __forceinline__ unsigned cvt_bf16x2(float lo, float hi) {
    unsigned r;
    asm("cvt.rn.bf16x2.f32 %0, %1, %2;" : "=r"(r) : "f"(hi), "f"(lo));  // d.hi=%1, d.lo=%2
    return r;
}
// named barrier over 128 threads (one split-K half)
__device__ __forceinline__ void half_bar(int id) {
    asm volatile("bar.sync %0, %1;" :: "r"(id), "r"(128) : "memory");
}

// ---------------- scratch (static device memory; no allocation) ----------------
__device__ float    g_sq[NATOMS];
__device__ float    g_s0[NATOMS];
__device__ int      g_cnt[NATOMS];
__device__ int      g_cell[NATOMS];
__device__ int      g_cellcnt[NCELLS];
__device__ int      g_cellstart[NCELLS + 1];
__device__ int      g_cellptr[NCELLS];
__device__ int      g_cblk[CBLK];
__device__ __align__(16) float4 g_cellpos[NATOMS];   // (x, y, z, -0.5*sq)
__device__ unsigned g_keys[NATOMS];
__device__ unsigned g_hist[NBINS];
__device__ unsigned g_chist[NCHUNK];
__device__ int      g_H;
__device__ int      g_r;
__device__ int      g_m;
__device__ int      g_done;
__device__ ull      g_bbuf[NATOMS];
__device__ int      g_sel[NATOMS];
__device__ int      g_idx[NSEL];
__device__ __align__(16) __nv_bfloat16 g_qh[NSEL * HID];  // q * scale*log2e, hi part
__device__ __align__(16) __nv_bfloat16 g_ql[NSEL * HID];  // q residual
__device__ __align__(16) __nv_bfloat16 g_kh[NSEL * HID];  // k hi part
__device__ __align__(16) __nv_bfloat16 g_kl[NSEL * HID];  // k residual
__device__ __align__(16) __nv_bfloat16 g_vh[NSEL * HID];  // V hi part
__device__ __align__(16) __nv_bfloat16 g_vl[NSEL * HID];  // V residual
__device__ __align__(16) float g_av[NSEL * HID];
__device__ float    g_mav[HID];

// ---------------- 0: init (zero hist/chist/cellcnt/cnt + ligand center + base) ----------------
// grid = NCELLS/256 = 432 blocks (covers all zeroed ranges).
__global__ void k_init(const float* __restrict__ lig, const float* __restrict__ pos) {
    __shared__ float c3[3];
    int t = threadIdx.x;
    if (t < 32) {
        float x = lig[t * 3 + 0], y = lig[t * 3 + 1], z = lig[t * 3 + 2];
        #pragma unroll
        for (int o = 16; o > 0; o >>= 1) {
            x += __shfl_down_sync(0xFFFFFFFFu, x, o);
            y += __shfl_down_sync(0xFFFFFFFFu, y, o);
            z += __shfl_down_sync(0xFFFFFFFFu, z, o);
        }
        if (t == 0) {
            c3[0] = x * (1.0f / NLIG);
            c3[1] = y * (1.0f / NLIG);
            c3[2] = z * (1.0f / NLIG);
        }
    }
    __syncthreads();
    int gi = blockIdx.x * 256 + t;
    if (gi < NBINS) g_hist[gi] = 0;
    if (gi < NCHUNK) g_chist[gi] = 0;
    if (gi < NCELLS) g_cellcnt[gi] = 0;
    if (gi == 0) { g_m = 0; g_done = 0; }
    if (gi < NATOMS) {
        g_cnt[gi] = 0;
        float x = pos[gi * 3 + 0], y = pos[gi * 3 + 1], z = pos[gi * 3 + 2];
        g_sq[gi] = fmaf(z, z, fmaf(y, y, x * x));
        float dx = x - c3[0], dy = y - c3[1], dz = z - c3[2];
        float d = sqrtf(fmaf(dz, dz, fmaf(dy, dy, dx * dx)));
        g_s0[gi] = 1.0f / (1.0f + d / 5.0f);
    }
}

// ---------------- 1: assign cells + count ----------------
__global__ void k_cells(const float* __restrict__ pos) {
    int i = blockIdx.x * 256 + threadIdx.x;
    if (i >= NATOMS) return;
    float x = pos[i * 3 + 0], y = pos[i * 3 + 1], z = pos[i * 3 + 2];
    int cx = min(max((int)floorf(x * (1.0f / 3.0f)) + 24, 0), CDIM - 1);
    int cy = min(max((int)floorf(y * (1.0f / 3.0f)) + 24, 0), CDIM - 1);
    int cz = min(max((int)floorf(z * (1.0f / 3.0f)) + 24, 0), CDIM - 1);
    int cell = (cz * CDIM + cy) * CDIM + cx;
    g_cell[i] = cell;
    atomicAdd(&g_cellcnt[cell], 1);
}

// ---------------- 2: per-block cell-count sums ----------------
__global__ __launch_bounds__(256) void k_csum() {
    __shared__ int sm[256];
    int t = threadIdx.x;
    sm[t] = g_cellcnt[blockIdx.x * 256 + t];
    __syncthreads();
    for (int o = 128; o > 0; o >>= 1) {
        if (t < o) sm[t] += sm[t + o];
        __syncthreads();
    }
    if (t == 0) g_cblk[blockIdx.x] = sm[0];
}

// ---------------- 3: cell starts (brute re-sum of prior block sums + local prefix) ----------------
__global__ __launch_bounds__(256) void k_cstart() {
    __shared__ int sc[256];
    __shared__ int s_off;
    int t = threadIdx.x, b = blockIdx.x;
    int s = 0;
    for (int j = t; j < b; j += 256) s += g_cblk[j];
    sc[t] = s;
    __syncthreads();
    for (int o = 128; o > 0; o >>= 1) {
        if (t < o) sc[t] += sc[t + o];
        __syncthreads();
    }
    if (t == 0) s_off = sc[0];
    __syncthreads();
    int c = b * 256 + t;
    int cnt = g_cellcnt[c];
    sc[t] = cnt;
    __syncthreads();
    for (int o = 1; o < 256; o <<= 1) {
        int v = (t >= o) ? sc[t - o] : 0;
        __syncthreads();
        sc[t] += v;
        __syncthreads();
    }
    int start = s_off + sc[t] - cnt;   // exclusive prefix
    g_cellstart[c] = start;
    g_cellptr[c]   = start;
    if (b == 0 && t == 0) g_cellstart[NCELLS] = NATOMS;
}

// ---------------- 4: scatter atoms into cell-sorted packed array ----------------
__global__ void k_scatter(const float* __restrict__ pos) {
    int i = blockIdx.x * 256 + threadIdx.x;
    if (i >= NATOMS) return;
    int slot = atomicAdd(&g_cellptr[g_cell[i]], 1);
    g_cellpos[slot] = make_float4(pos[i * 3 + 0], pos[i * 3 + 1], pos[i * 3 + 2],
                                  -0.5f * g_sq[i]);
}

// ---------------- 5: neighbor counting via cells (61x less pair work) ----------------
// Split s=0..8 covers (dy,dz); the 3 x-adjacent cells are contiguous in cell id
// -> one contiguous candidate range. Same fmaf association as the proven
// all-pairs version: v = fma(px,qx, fma(py,qy, fma(pz,qz, w+ci))), count v>0.
__global__ __launch_bounds__(256) void k_neighbor(const float* __restrict__ pos) {
    int i = blockIdx.x * 256 + threadIdx.x;
    int s = blockIdx.y;                 // 0..8
    int dy = s % 3 - 1, dz = s / 3 - 1;
    float px = pos[i * 3 + 0], py = pos[i * 3 + 1], pz = pos[i * 3 + 2];
    float ci = 4.5f - 0.5f * g_sq[i];
    int cell = g_cell[i];
    int cx = cell % CDIM;
    int cy = (cell / CDIM) % CDIM;
    int cz = cell / (CDIM * CDIM);
    int ny = cy + dy, nz = cz + dz;
    int cnt = 0;
    if (ny >= 0 && ny < CDIM && nz >= 0 && nz < CDIM) {
        int rowbase = (nz * CDIM + ny) * CDIM;
        int lo = rowbase + max(cx - 1, 0);
        int hi = rowbase + min(cx + 1, CDIM - 1);
        int a = g_cellstart[lo];
        int b = g_cellstart[hi + 1];
        #pragma unroll 4
        for (int j = a; j < b; j++) {
            float4 q = g_cellpos[j];
            float v = fmaf(px, q.x, fmaf(py, q.y, fmaf(pz, q.z, q.w + ci)));
            cnt += (v > 0.0f);
        }
    }
    atomicAdd(&g_cnt[i], cnt);
}

// ---------------- 6: final scores -> sortable keys + fine & coarse histograms ----------------
__global__ void k_scorekey() {
    int i = blockIdx.x * blockDim.x + threadIdx.x;
    if (i >= NATOMS) return;
    float surface = 1.0f / (float)g_cnt[i];
    float s = g_s0[i] + 0.5f * surface;
    unsigned key = __float_as_uint(s);
    g_keys[i] = key;
    atomicAdd(&g_hist[key >> 16], 1u);
    atomicAdd(&g_chist[key >> 22], 1u);   // 64-bin chunk
}

// ---------------- 7: threshold bin — parallel over chunk hist ----------------
__global__ __launch_bounds__(1024) void k_scan() {
    __shared__ unsigned csum[NCHUNK];
    __shared__ unsigned hs[64];
    __shared__ int s_chunk;
    __shared__ unsigned s_above;
    int t = threadIdx.x;
    csum[t] = g_chist[t];
    __syncthreads();
    for (int o = 1; o < NCHUNK; o <<= 1) {
        unsigned v = (t + o < NCHUNK) ? csum[t + o] : 0u;
        __syncthreads();
        csum[t] += v;
        __syncthreads();
    }
    {
        unsigned mine = csum[t];
        unsigned nxt = (t + 1 < NCHUNK) ? csum[t + 1] : 0u;
        if (mine >= (unsigned)NSEL && nxt < (unsigned)NSEL) { s_chunk = t; s_above = nxt; }
    }
    __syncthreads();
    int chunk = s_chunk;
    unsigned above = s_above;
    if (t < 64) hs[t] = g_hist[chunk * 64 + t];
    __syncthreads();
    for (int o = 1; o < 64; o <<= 1) {
        unsigned v = (t < 64 && t + o < 64) ? hs[t + o] : 0u;
        __syncthreads();
        if (t < 64) hs[t] += v;
        __syncthreads();
    }
    if (t < 64) {
        unsigned mine = above + hs[t];
        unsigned nxt  = above + ((t + 1 < 64) ? hs[t + 1] : 0u);
        if (mine >= (unsigned)NSEL && nxt < (unsigned)NSEL) {
            g_H = chunk * 64 + t;
            g_r = (int)((unsigned)NSEL - nxt);
        }
    }
}

// ---------------- 8: boundary-bin elements ----------------
__global__ void k_boundary() {
    int i = blockIdx.x * blockDim.x + threadIdx.x;
    if (i >= NATOMS) return;
    unsigned key = g_keys[i];
    if ((int)(key >> 16) == g_H) {
        int p = atomicAdd(&g_m, 1);
        g_bbuf[p] = ((ull)key << 32) | (ull)(0xFFFFFFFFu - (unsigned)i);
    }
}

// ---------------- 9: selection flags ----------------
__global__ void k_flags() {
    int i = blockIdx.x * blockDim.x + threadIdx.x;
    if (i >= NATOMS) return;
    unsigned key = g_keys[i];
    int hi = (int)(key >> 16);
    int s = 0;
    if (hi > g_H) s = 1;
    else if (hi == g_H) {
        ull mine = ((ull)key << 32) | (ull)(0xFFFFFFFFu - (unsigned)i);
        int m = g_m, cnt = 0, r = g_r;
        for (int t = 0; t < m; t++) cnt += (g_bbuf[t] > mine);
        if (cnt < r) s = 1;
    }
    g_sel[i] = s;
}

// ---------------- 10: single-pass deterministic compaction ----------------
__global__ __launch_bounds__(256) void k_compact_all() {
    __shared__ int sc[256];
    __shared__ int s_off;
    int t = threadIdx.x, b = blockIdx.x;
    int pre = b * 256;
    int s = 0;
    for (int j = t; j < pre; j += 256) s += g_sel[j];
    sc[t] = s;
    __syncthreads();
    for (int o = 128; o > 0; o >>= 1) {
        if (t < o) sc[t] += sc[t + o];
        __syncthreads();
    }
    if (t == 0) s_off = sc[0];
    __syncthreads();
    int i = pre + t;
    int f = g_sel[i];
    sc[t] = f;
    __syncthreads();
    for (int o = 1; o < 256; o <<= 1) {
        int v = (t >= o) ? sc[t - o] : 0;
        __syncthreads();
        sc[t] += v;
        __syncthreads();
    }
    if (f) g_idx[s_off + sc[t] - 1] = i;
}

// ---------------- 11: gather + embed + QKV (16 rows/block; bf16 hi/lo outputs) ----------------
__global__ __launch_bounds__(256) void k_qkv(
    const float* __restrict__ x,
    const float* __restrict__ Wn, const float* __restrict__ bn,
    const float* __restrict__ Wq, const float* __restrict__ bq,
    const float* __restrict__ Wk, const float* __restrict__ bk,
    const float* __restrict__ Wv, const float* __restrict__ bv)
{
    __shared__ float hs[16][HID];
    int t = threadIdx.x;
    int c = t & 127;          // column
    int half = t >> 7;        // 0/1 -> rows 0-7 / 8-15
    int r0 = blockIdx.x * 16;
    #pragma unroll
    for (int k = 0; k < 8; k++) {
        int rr = half * 8 + k;
        int row = g_idx[r0 + rr];
        const float* xr = x + row * NODE_F;
        float acc = bn[c];
        #pragma unroll
        for (int f = 0; f < NODE_F; f++) acc = fmaf(__ldg(xr + f), Wn[f * HID + c], acc);
        hs[rr][c] = acc;
    }
    __syncthreads();
    float aq[8], ak[8], av[8];
    #pragma unroll
    for (int rr = 0; rr < 8; rr++) { aq[rr] = bq[c]; ak[rr] = bk[c]; av[rr] = bv[c]; }
    for (int d = 0; d < HID; d++) {
        float wq = Wq[d * HID + c], wk = Wk[d * HID + c], wv = Wv[d * HID + c];
        #pragma unroll
        for (int rr = 0; rr < 8; rr++) {
            float h = hs[half * 8 + rr][d];
            aq[rr] = fmaf(h, wq, aq[rr]);
            ak[rr] = fmaf(h, wk, ak[rr]);
            av[rr] = fmaf(h, wv, av[rr]);
        }
    }
    const float cs = 0.25f * 1.4426950408889634f;  // scale * log2(e), folded into Q
    #pragma unroll
    for (int rr = 0; rr < 8; rr++) {
        int o = (r0 + half * 8 + rr) * HID + c;
        float qs = aq[rr] * cs;
        __nv_bfloat16 qhi = __float2bfloat16(qs);
        g_qh[o] = qhi;
        g_ql[o] = __float2bfloat16(qs - __bfloat162float(qhi));
        float kf = ak[rr];
        __nv_bfloat16 khi = __float2bfloat16(kf);
        g_kh[o] = khi;
        g_kl[o] = __float2bfloat16(kf - __bfloat162float(khi));
        float vf = av[rr];
        __nv_bfloat16 vhi = __float2bfloat16(vf);
        g_vh[o] = vhi;
        g_vl[o] = __float2bfloat16(vf - __bfloat162float(vhi));
    }
}

// ---------------- 12: tensor-core attention, intra-block split-K x2 (proven R11) ----------------
__global__ __launch_bounds__(256) void k_attn_tc() {
    __shared__ __align__(16) char sraw[8 * TILEB];   // exactly 48KB

    int h    = blockIdx.y;
    int q0   = blockIdx.x * TQ;
    int tid  = threadIdx.x;
    int warp = tid >> 5;
    int lane = tid & 31;
    int qw   = warp & 3;      // query sub-tile (16 rows)
    int half = warp >> 2;     // split-K half
    int lt   = tid & 127;     // thread index within half

    __nv_bfloat16 (*sKh)[KPAD] = (__nv_bfloat16 (*)[KPAD])(sraw + half * 4 * TILEB + 0 * TILEB);
    __nv_bfloat16 (*sKl)[KPAD] = (__nv_bfloat16 (*)[KPAD])(sraw + half * 4 * TILEB + 1 * TILEB);
    __nv_bfloat16 (*sVh)[KPAD] = (__nv_bfloat16 (*)[KPAD])(sraw + half * 4 * TILEB + 2 * TILEB);
    __nv_bfloat16 (*sVl)[KPAD] = (__nv_bfloat16 (*)[KPAD])(sraw + half * 4 * TILEB + 3 * TILEB);

    // ---- stage Q tile (64 rows x 16 cols, hi+lo) into half-0 K buffers ----
    {
        __nv_bfloat16 (*qH)[KPAD] = (__nv_bfloat16 (*)[KPAD])(sraw);
        __nv_bfloat16 (*qL)[KPAD] = (__nv_bfloat16 (*)[KPAD])(sraw + TILEB);
        if (tid < 128) {
            int row = tid >> 1, hf = tid & 1;
            *(uint4*)&qH[row][hf * 8] = *(const uint4*)(g_qh + (q0 + row) * HID + h * DH + hf * 8);
            *(uint4*)&qL[row][hf * 8] = *(const uint4*)(g_ql + (q0 + row) * HID + h * DH + hf * 8);
        }
        __syncthreads();
    }
    unsigned a_hi[4], a_lo[4];
    {
        __nv_bfloat16 (*qH)[KPAD] = (__nv_bfloat16 (*)[KPAD])(sraw);
        __nv_bfloat16 (*qL)[KPAD] = (__nv_bfloat16 (*)[KPAD])(sraw + TILEB);
        int mrow = qw * 16 + ((lane >> 3) & 1) * 8 + (lane & 7);
        unsigned coff = (lane >> 4) * 16;
        ldm_x4(a_hi, scvt(&qH[mrow][0]) + coff);
        ldm_x4(a_lo, scvt(&qL[mrow][0]) + coff);
    }
    __syncthreads();

    float o[8];
    #pragma unroll
    for (int i = 0; i < 8; i++) o[i] = 0.0f;
    float l0 = 0.0f, l1 = 0.0f;

    int brow8  = lane & 7;                            // QK B: 8 key rows, d halves
    unsigned bcoff = ((lane >> 3) & 1) * 16;
    int vrow16 = (lane & 7) + ((lane >> 3) & 1) * 8;  // PV B: 16 key rows
    int bar_id = 1 + half;

    for (int it = 0; it < 16; it++) {
        int kt = half * 16 + it;
        {
            int src = (kt * TK + lt) * HID + h * DH;
            const uint4* kh = (const uint4*)(g_kh + src);
            const uint4* kl = (const uint4*)(g_kl + src);
            const uint4* vh = (const uint4*)(g_vh + src);
            const uint4* vl = (const uint4*)(g_vl + src);
            *(uint4*)&sKh[lt][0] = kh[0]; *(uint4*)&sKh[lt][8] = kh[1];
            *(uint4*)&sKl[lt][0] = kl[0]; *(uint4*)&sKl[lt][8] = kl[1];
            *(uint4*)&sVh[lt][0] = vh[0]; *(uint4*)&sVh[lt][8] = vh[1];
            *(uint4*)&sVl[lt][0] = vl[0]; *(uint4*)&sVl[lt][8] = vl[1];
        }
        half_bar(bar_id);

        #pragma unroll
        for (int g16 = 0; g16 < TK / 16; g16++) {
            float S[8];
            #pragma unroll
            for (int i = 0; i < 8; i++) S[i] = 0.0f;
            #pragma unroll
            for (int half8 = 0; half8 < 2; half8++) {
                int kb = g16 * 16 + half8 * 8 + brow8;
                unsigned bh[2], bl[2];
                ldm_x2(bh, scvt(&sKh[kb][0]) + bcoff);
                ldm_x2(bl, scvt(&sKl[kb][0]) + bcoff);
                float* Sd = S + half8 * 4;
                mma16816(Sd, a_hi, bh);
                mma16816(Sd, a_hi, bl);
                mma16816(Sd, a_lo, bh);
            }
            float p0 = ex2(S[0]), p1 = ex2(S[1]), p2 = ex2(S[2]), p3 = ex2(S[3]);
            float p4 = ex2(S[4]), p5 = ex2(S[5]), p6 = ex2(S[6]), p7 = ex2(S[7]);
            l0 += (p0 + p1) + (p4 + p5);   // D rows r0
            l1 += (p2 + p3) + (p6 + p7);   // D rows r0+8
            unsigned pa[4];
            pa[0] = cvt_bf16x2(p0, p1);
            pa[1] = cvt_bf16x2(p2, p3);
            pa[2] = cvt_bf16x2(p4, p5);
            pa[3] = cvt_bf16x2(p6, p7);
            int vr = g16 * 16 + vrow16;
            #pragma unroll
            for (int dh2 = 0; dh2 < 2; dh2++) {
                unsigned bvh[2], bvl[2];
                ldm_x2t(bvh, scvt(&sVh[vr][dh2 * 8]));
                ldm_x2t(bvl, scvt(&sVl[vr][dh2 * 8]));
                mma16816(o + dh2 * 4, pa, bvh);
                mma16816(o + dh2 * 4, pa, bvl);
            }
        }
        half_bar(bar_id);
    }

    // ---- combine the two K-halves (smem overlay on dead tile buffers) ----
    __syncthreads();
    float* sO = (float*)sraw;
    if (half == 1) {
        float* dst = sO + (qw * 32 + lane) * 10;
        #pragma unroll
        for (int i = 0; i < 8; i++) dst[i] = o[i];
        dst[8] = l0; dst[9] = l1;
    }
    __syncthreads();
    if (half == 1) return;

    {
        const float* srcp = sO + (qw * 32 + lane) * 10;
        #pragma unroll
        for (int i = 0; i < 8; i++) o[i] += srcp[i];
        l0 += srcp[8]; l1 += srcp[9];
    }
    l0 += __shfl_xor_sync(0xFFFFFFFFu, l0, 1);
    l0 += __shfl_xor_sync(0xFFFFFFFFu, l0, 2);
    l1 += __shfl_xor_sync(0xFFFFFFFFu, l1, 1);
    l1 += __shfl_xor_sync(0xFFFFFFFFu, l1, 2);
    float inv0 = 1.0f / l0, inv1 = 1.0f / l1;

    int r0c = lane >> 2;
    int cc  = (lane & 3) * 2;
    int row0 = q0 + qw * 16 + r0c;
    int row1 = row0 + 8;
    float* d0 = g_av + row0 * HID + h * DH;
    float* d1 = g_av + row1 * HID + h * DH;
    d0[cc]     = o[0] * inv0;  d0[cc + 1] = o[1] * inv0;
    d1[cc]     = o[2] * inv1;  d1[cc + 1] = o[3] * inv1;
    d0[cc + 8] = o[4] * inv0;  d0[cc + 9] = o[5] * inv0;
    d1[cc + 8] = o[6] * inv1;  d1[cc + 9] = o[7] * inv1;
}

// ---------------- 13: column mean + (last block) Wo/MLP head ----------------
__global__ __launch_bounds__(256) void k_colsum_final(
    const float* __restrict__ Wo, const float* __restrict__ bo,
    const float* __restrict__ W1, const float* __restrict__ b1,
    const float* __restrict__ W2, const float* __restrict__ b2,
    float* __restrict__ out)
{
    __shared__ float sm[256];
    __shared__ int is_last;
    int col = blockIdx.x;
    int t = threadIdx.x;
    float s = 0.0f;
    for (int r = t; r < NSEL; r += 256) s += g_av[r * HID + col];
    sm[t] = s;
    __syncthreads();
    for (int o = 128; o > 0; o >>= 1) {
        if (t < o) sm[t] += sm[t + o];
        __syncthreads();
    }
    if (t == 0) {
        g_mav[col] = sm[0] * (1.0f / NSEL);
        __threadfence();
        is_last = (atomicAdd(&g_done, 1) == HID - 1);
    }
    __syncthreads();
    if (!is_last) return;

    __shared__ float mav[HID];
    __shared__ float pooled[HID];
    __shared__ float t1[OUTD];
    if (t < HID) mav[t] = g_mav[t];
    __syncthreads();
    if (t < HID) {
        float acc = bo[t];
        for (int d = 0; d < HID; d++) acc = fmaf(mav[d], Wo[d * HID + t], acc);
        pooled[t] = acc;
    }
    __syncthreads();
    {
        float acc = b1[t];
        for (int d = 0; d < HID; d++) acc = fmaf(pooled[d], W1[d * OUTD + t], acc);
        t1[t] = fmaxf(acc, 0.0f);
    }
    __syncthreads();
    {
        float acc = b2[t];
        for (int d = 0; d < OUTD; d++) acc = fmaf(t1[d], W2[d * OUTD + t], acc);
        out[t] = acc;
    }
}

// ---------------- launcher ----------------
extern "C" void kernel_launch(void* const* d_in, const int* in_sizes, int n_in,
                              void* d_out, int out_size)
{
    const float* x    = (const float*)d_in[0];
    const float* pos  = (const float*)d_in[1];
    const float* lig  = (const float*)d_in[2];
    const float* Wn   = (const float*)d_in[3];
    const float* bn   = (const float*)d_in[4];
    const float* Wq   = (const float*)d_in[5];
    const float* bq   = (const float*)d_in[6];
    const float* Wk   = (const float*)d_in[7];
    const float* bk   = (const float*)d_in[8];
    const float* Wv   = (const float*)d_in[9];
    const float* bv   = (const float*)d_in[10];
    const float* Wo   = (const float*)d_in[11];
    const float* bo   = (const float*)d_in[12];
    const float* W1   = (const float*)d_in[13];
    const float* b1   = (const float*)d_in[14];
    const float* W2   = (const float*)d_in[15];
    const float* b2   = (const float*)d_in[16];
    float* out = (float*)d_out;

    k_init<<<CBLK, 256>>>(lig, pos);
    k_cells<<<NATOMS / 256, 256>>>(pos);
    k_csum<<<CBLK, 256>>>();
    k_cstart<<<CBLK, 256>>>();
    k_scatter<<<NATOMS / 256, 256>>>(pos);
    k_neighbor<<<dim3(NATOMS / 256, 9), 256>>>(pos);
    k_scorekey<<<NATOMS / 256, 256>>>();
    k_scan<<<1, 1024>>>();
    k_boundary<<<NATOMS / 256, 256>>>();
    k_flags<<<NATOMS / 256, 256>>>();
    k_compact_all<<<64, 256>>>();
    k_qkv<<<NSEL / 16, 256>>>(x, Wn, bn, Wq, bq, Wk, bk, Wv, bv);
    k_attn_tc<<<dim3(NSEL / TQ, HEADS), 256>>>();
    k_colsum_final<<<HID, 256>>>(Wo, bo, W1, b1, W2, b2, out);
}

// round 14
// speedup vs baseline: 1.7053x; 1.2197x over previous
#include <cuda_runtime.h>
#include <cuda_bf16.h>
#include <cuda_fp16.h>
#include <stdint.h>

// ---------------- problem constants ----------------
#define NATOMS   16384
#define NSEL     4096
#define NODE_F   8
#define HID      128
#define HEADS    8
#define DH       16
#define OUTD     256
#define NLIG     32
#define NBINS    65536
#define NCHUNK   1024     // coarse chunks of 64 fine bins
#define CDIM     48       // spatial cells per axis (cell size 3.0)
#define NCELLS   (CDIM * CDIM * CDIM)   // 110592
#define CBLK     (NCELLS / 256)         // 432 blocks over cells

#define TQ 64      // queries per attention block (16 per warp-quad)
#define TK 128     // keys per smem tile
#define KPAD 24    // smem row stride in fp16 (48B: 16B-aligned, ldmatrix conflict-free)
#define TILEB (TK * KPAD * 2)   // 6144 bytes per tile array

// softmax range shift (log2 units): p = 2^(S - SHIFT). Shift cancels exactly in
// o/l; it moves P into fp16's representable range (overflow now needs a
// >16.6-sigma logit; underflowed weights are < 2^-16 relative — negligible).
#define SM_SHIFT 8.0f

typedef unsigned long long ull;

// ---------------- helpers ----------------
__device__ __forceinline__ float ex2(float x) {
    float r; asm("ex2.approx.f32 %0, %1;" : "=f"(r) : "f"(x)); return r;
}
__device__ __forceinline__ unsigned scvt(const void* p) {
    return (unsigned)__cvta_generic_to_shared(p);
}
__device__ __forceinline__ void ldm_x4(unsigned* r, unsigned a) {
    asm volatile("ldmatrix.sync.aligned.m8n8.x4.shared.b16 {%0,%1,%2,%3}, [%4];"
        : "=r"(r[0]), "=r"(r[1]), "=r"(r[2]), "=r"(r[3]) : "r"(a));
}
__device__ __forceinline__ void ldm_x4t(unsigned* r, unsigned a) {
    asm volatile("ldmatrix.sync.aligned.m8n8.x4.trans.shared.b16 {%0,%1,%2,%3}, [%4];"
        : "=r"(r[0]), "=r"(r[1]), "=r"(r[2]), "=r"(r[3]) : "r"(a));
}
// fp16 MMA, fp32 accumulate
__device__ __forceinline__ void mma16816f(float* d, const unsigned* a, const unsigned* b) {
    asm volatile(
        "mma.sync.aligned.m16n8k16.row.col.f32.f16.f16.f32 "
        "{%0,%1,%2,%3}, {%4,%5,%6,%7}, {%8,%9}, {%0,%1,%2,%3};"
        : "+f"(d[0]), "+f"(d[1]), "+f"(d[2]), "+f"(d[3])
        : "r"(a[0]), "r"(a[1]), "r"(a[2]), "r"(a[3]), "r"(b[0]), "r"(b[1]));
}
// saturating pack: clamps to +/-65504 instead of producing inf (safety net)
__device__ __forceinline__ unsigned cvt_f16x2(float lo, float hi) {
    unsigned r;
    asm("cvt.rn.satfinite.f16x2.f32 %0, %1, %2;" : "=r"(r) : "f"(hi), "f"(lo));  // d.hi=%1
    return r;
}
// named barrier over 128 threads (one split-K half)
__device__ __forceinline__ void half_bar(int id) {
    asm volatile("bar.sync %0, %1;" :: "r"(id), "r"(128) : "memory");
}

// ---------------- scratch (static device memory; no allocation) ----------------
__device__ float    g_sq[NATOMS];
__device__ float    g_s0[NATOMS];
__device__ int      g_cnt[NATOMS];
__device__ int      g_cell[NATOMS];
__device__ int      g_cellcnt[NCELLS];
__device__ int      g_cellstart[NCELLS + 1];
__device__ int      g_cellptr[NCELLS];
__device__ int      g_cblk[CBLK];
__device__ __align__(16) float4 g_cellpos[NATOMS];   // (x, y, z, -0.5*sq)
__device__ unsigned g_keys[NATOMS];
__device__ unsigned g_hist[NBINS];
__device__ unsigned g_chist[NCHUNK];
__device__ int      g_H;
__device__ int      g_r;
__device__ int      g_m;
__device__ int      g_done;
__device__ ull      g_bbuf[NATOMS];
__device__ int      g_sel[NATOMS];
__device__ int      g_idx[NSEL];
__device__ __align__(16) __half g_qf[NSEL * HID];   // q * scale*log2e (fp16)
__device__ __align__(16) __half g_kf[NSEL * HID];   // k (fp16)
__device__ __align__(16) __half g_vhf[NSEL * HID];  // V hi (fp16)
__device__ __align__(16) __half g_vlf[NSEL * HID];  // V residual (fp16)
__device__ __align__(16) float g_av[NSEL * HID];
__device__ float    g_mav[HID];

// ---------------- 0: init (zero hist/chist/cellcnt/cnt + ligand center + base) ----------------
__global__ void k_init(const float* __restrict__ lig, const float* __restrict__ pos) {
    __shared__ float c3[3];
    int t = threadIdx.x;
    if (t < 32) {
        float x = lig[t * 3 + 0], y = lig[t * 3 + 1], z = lig[t * 3 + 2];
        #pragma unroll
        for (int o = 16; o > 0; o >>= 1) {
            x += __shfl_down_sync(0xFFFFFFFFu, x, o);
            y += __shfl_down_sync(0xFFFFFFFFu, y, o);
            z += __shfl_down_sync(0xFFFFFFFFu, z, o);
        }
        if (t == 0) {
            c3[0] = x * (1.0f / NLIG);
            c3[1] = y * (1.0f / NLIG);
            c3[2] = z * (1.0f / NLIG);
        }
    }
    __syncthreads();
    int gi = blockIdx.x * 256 + t;
    if (gi < NBINS) g_hist[gi] = 0;
    if (gi < NCHUNK) g_chist[gi] = 0;
    if (gi < NCELLS) g_cellcnt[gi] = 0;
    if (gi == 0) { g_m = 0; g_done = 0; }
    if (gi < NATOMS) {
        g_cnt[gi] = 0;
        float x = pos[gi * 3 + 0], y = pos[gi * 3 + 1], z = pos[gi * 3 + 2];
        g_sq[gi] = fmaf(z, z, fmaf(y, y, x * x));
        float dx = x - c3[0], dy = y - c3[1], dz = z - c3[2];
        float d = sqrtf(fmaf(dz, dz, fmaf(dy, dy, dx * dx)));
        g_s0[gi] = 1.0f / (1.0f + d / 5.0f);
    }
}

// ---------------- 1: assign cells + count ----------------
__global__ void k_cells(const float* __restrict__ pos) {
    int i = blockIdx.x * 256 + threadIdx.x;
    if (i >= NATOMS) return;
    float x = pos[i * 3 + 0], y = pos[i * 3 + 1], z = pos[i * 3 + 2];
    int cx = min(max((int)floorf(x * (1.0f / 3.0f)) + 24, 0), CDIM - 1);
    int cy = min(max((int)floorf(y * (1.0f / 3.0f)) + 24, 0), CDIM - 1);
    int cz = min(max((int)floorf(z * (1.0f / 3.0f)) + 24, 0), CDIM - 1);
    int cell = (cz * CDIM + cy) * CDIM + cx;
    g_cell[i] = cell;
    atomicAdd(&g_cellcnt[cell], 1);
}

// ---------------- 2: per-block cell-count sums ----------------
__global__ __launch_bounds__(256) void k_csum() {
    __shared__ int sm[256];
    int t = threadIdx.x;
    sm[t] = g_cellcnt[blockIdx.x * 256 + t];
    __syncthreads();
    for (int o = 128; o > 0; o >>= 1) {
        if (t < o) sm[t] += sm[t + o];
        __syncthreads();
    }
    if (t == 0) g_cblk[blockIdx.x] = sm[0];
}

// ---------------- 3: cell starts ----------------
__global__ __launch_bounds__(256) void k_cstart() {
    __shared__ int sc[256];
    __shared__ int s_off;
    int t = threadIdx.x, b = blockIdx.x;
    int s = 0;
    for (int j = t; j < b; j += 256) s += g_cblk[j];
    sc[t] = s;
    __syncthreads();
    for (int o = 128; o > 0; o >>= 1) {
        if (t < o) sc[t] += sc[t + o];
        __syncthreads();
    }
    if (t == 0) s_off = sc[0];
    __syncthreads();
    int c = b * 256 + t;
    int cnt = g_cellcnt[c];
    sc[t] = cnt;
    __syncthreads();
    for (int o = 1; o < 256; o <<= 1) {
        int v = (t >= o) ? sc[t - o] : 0;
        __syncthreads();
        sc[t] += v;
        __syncthreads();
    }
    int start = s_off + sc[t] - cnt;   // exclusive prefix
    g_cellstart[c] = start;
    g_cellptr[c]   = start;
    if (b == 0 && t == 0) g_cellstart[NCELLS] = NATOMS;
}

// ---------------- 4: scatter atoms into cell-sorted packed array ----------------
__global__ void k_scatter(const float* __restrict__ pos) {
    int i = blockIdx.x * 256 + threadIdx.x;
    if (i >= NATOMS) return;
    int slot = atomicAdd(&g_cellptr[g_cell[i]], 1);
    g_cellpos[slot] = make_float4(pos[i * 3 + 0], pos[i * 3 + 1], pos[i * 3 + 2],
                                  -0.5f * g_sq[i]);
}

// ---------------- 5: neighbor counting via cells ----------------
__global__ __launch_bounds__(256) void k_neighbor(const float* __restrict__ pos) {
    int i = blockIdx.x * 256 + threadIdx.x;
    int s = blockIdx.y;                 // 0..8
    int dy = s % 3 - 1, dz = s / 3 - 1;
    float px = pos[i * 3 + 0], py = pos[i * 3 + 1], pz = pos[i * 3 + 2];
    float ci = 4.5f - 0.5f * g_sq[i];
    int cell = g_cell[i];
    int cx = cell % CDIM;
    int cy = (cell / CDIM) % CDIM;
    int cz = cell / (CDIM * CDIM);
    int ny = cy + dy, nz = cz + dz;
    int cnt = 0;
    if (ny >= 0 && ny < CDIM && nz >= 0 && nz < CDIM) {
        int rowbase = (nz * CDIM + ny) * CDIM;
        int lo = rowbase + max(cx - 1, 0);
        int hi = rowbase + min(cx + 1, CDIM - 1);
        int a = g_cellstart[lo];
        int b = g_cellstart[hi + 1];
        #pragma unroll 4
        for (int j = a; j < b; j++) {
            float4 q = g_cellpos[j];
            float v = fmaf(px, q.x, fmaf(py, q.y, fmaf(pz, q.z, q.w + ci)));
            cnt += (v > 0.0f);
        }
    }
    atomicAdd(&g_cnt[i], cnt);
}

// ---------------- 6: final scores -> sortable keys + fine & coarse histograms ----------------
__global__ void k_scorekey() {
    int i = blockIdx.x * blockDim.x + threadIdx.x;
    if (i >= NATOMS) return;
    float surface = 1.0f / (float)g_cnt[i];
    float s = g_s0[i] + 0.5f * surface;
    unsigned key = __float_as_uint(s);
    g_keys[i] = key;
    atomicAdd(&g_hist[key >> 16], 1u);
    atomicAdd(&g_chist[key >> 22], 1u);   // 64-bin chunk
}

// ---------------- 7: threshold bin — parallel over chunk hist ----------------
__global__ __launch_bounds__(1024) void k_scan() {
    __shared__ unsigned csum[NCHUNK];
    __shared__ unsigned hs[64];
    __shared__ int s_chunk;
    __shared__ unsigned s_above;
    int t = threadIdx.x;
    csum[t] = g_chist[t];
    __syncthreads();
    for (int o = 1; o < NCHUNK; o <<= 1) {
        unsigned v = (t + o < NCHUNK) ? csum[t + o] : 0u;
        __syncthreads();
        csum[t] += v;
        __syncthreads();
    }
    {
        unsigned mine = csum[t];
        unsigned nxt = (t + 1 < NCHUNK) ? csum[t + 1] : 0u;
        if (mine >= (unsigned)NSEL && nxt < (unsigned)NSEL) { s_chunk = t; s_above = nxt; }
    }
    __syncthreads();
    int chunk = s_chunk;
    unsigned above = s_above;
    if (t < 64) hs[t] = g_hist[chunk * 64 + t];
    __syncthreads();
    for (int o = 1; o < 64; o <<= 1) {
        unsigned v = (t < 64 && t + o < 64) ? hs[t + o] : 0u;
        __syncthreads();
        if (t < 64) hs[t] += v;
        __syncthreads();
    }
    if (t < 64) {
        unsigned mine = above + hs[t];
        unsigned nxt  = above + ((t + 1 < 64) ? hs[t + 1] : 0u);
        if (mine >= (unsigned)NSEL && nxt < (unsigned)NSEL) {
            g_H = chunk * 64 + t;
            g_r = (int)((unsigned)NSEL - nxt);
        }
    }
}

// ---------------- 8: boundary-bin elements ----------------
__global__ void k_boundary() {
    int i = blockIdx.x * blockDim.x + threadIdx.x;
    if (i >= NATOMS) return;
    unsigned key = g_keys[i];
    if ((int)(key >> 16) == g_H) {
        int p = atomicAdd(&g_m, 1);
        g_bbuf[p] = ((ull)key << 32) | (ull)(0xFFFFFFFFu - (unsigned)i);
    }
}

// ---------------- 9: selection flags ----------------
__global__ void k_flags() {
    int i = blockIdx.x * blockDim.x + threadIdx.x;
    if (i >= NATOMS) return;
    unsigned key = g_keys[i];
    int hi = (int)(key >> 16);
    int s = 0;
    if (hi > g_H) s = 1;
    else if (hi == g_H) {
        ull mine = ((ull)key << 32) | (ull)(0xFFFFFFFFu - (unsigned)i);
        int m = g_m, cnt = 0, r = g_r;
        for (int t = 0; t < m; t++) cnt += (g_bbuf[t] > mine);
        if (cnt < r) s = 1;
    }
    g_sel[i] = s;
}

// ---------------- 10: single-pass deterministic compaction ----------------
__global__ __launch_bounds__(256) void k_compact_all() {
    __shared__ int sc[256];
    __shared__ int s_off;
    int t = threadIdx.x, b = blockIdx.x;
    int pre = b * 256;
    int s = 0;
    for (int j = t; j < pre; j += 256) s += g_sel[j];
    sc[t] = s;
    __syncthreads();
    for (int o = 128; o > 0; o >>= 1) {
        if (t < o) sc[t] += sc[t + o];
        __syncthreads();
    }
    if (t == 0) s_off = sc[0];
    __syncthreads();
    int i = pre + t;
    int f = g_sel[i];
    sc[t] = f;
    __syncthreads();
    for (int o = 1; o < 256; o <<= 1) {
        int v = (t >= o) ? sc[t - o] : 0;
        __syncthreads();
        sc[t] += v;
        __syncthreads();
    }
    if (f) g_idx[s_off + sc[t] - 1] = i;
}

// ---------------- 11: gather + embed + QKV (fp16 outputs; V hi/lo split) ----------------
__global__ __launch_bounds__(256) void k_qkv(
    const float* __restrict__ x,
    const float* __restrict__ Wn, const float* __restrict__ bn,
    const float* __restrict__ Wq, const float* __restrict__ bq,
    const float* __restrict__ Wk, const float* __restrict__ bk,
    const float* __restrict__ Wv, const float* __restrict__ bv)
{
    __shared__ float hs[16][HID];
    int t = threadIdx.x;
    int c = t & 127;          // column
    int half = t >> 7;        // 0/1 -> rows 0-7 / 8-15
    int r0 = blockIdx.x * 16;
    #pragma unroll
    for (int k = 0; k < 8; k++) {
        int rr = half * 8 + k;
        int row = g_idx[r0 + rr];
        const float* xr = x + row * NODE_F;
        float acc = bn[c];
        #pragma unroll
        for (int f = 0; f < NODE_F; f++) acc = fmaf(__ldg(xr + f), Wn[f * HID + c], acc);
        hs[rr][c] = acc;
    }
    __syncthreads();
    float aq[8], ak[8], av[8];
    #pragma unroll
    for (int rr = 0; rr < 8; rr++) { aq[rr] = bq[c]; ak[rr] = bk[c]; av[rr] = bv[c]; }
    for (int d = 0; d < HID; d++) {
        float wq = Wq[d * HID + c], wk = Wk[d * HID + c], wv = Wv[d * HID + c];
        #pragma unroll
        for (int rr = 0; rr < 8; rr++) {
            float h = hs[half * 8 + rr][d];
            aq[rr] = fmaf(h, wq, aq[rr]);
            ak[rr] = fmaf(h, wk, ak[rr]);
            av[rr] = fmaf(h, wv, av[rr]);
        }
    }
    const float cs = 0.25f * 1.4426950408889634f;  // scale * log2(e), folded into Q
    #pragma unroll
    for (int rr = 0; rr < 8; rr++) {
        int o = (r0 + half * 8 + rr) * HID + c;
        g_qf[o] = __float2half_rn(aq[rr] * cs);
        g_kf[o] = __float2half_rn(ak[rr]);
        float vf = av[rr];
        __half vhi = __float2half_rn(vf);
        g_vhf[o] = vhi;
        g_vlf[o] = __float2half_rn(vf - __half2float(vhi));
    }
}

// ---------------- 12: tensor-core attention, fp16, intra-block split-K x2 ----------------
// S = Q(fp16)·K(fp16), fp32 accum, initialized to -SM_SHIFT: p = 2^(S-8).
// The shift cancels exactly in o/l but moves P into fp16 range (R13 failed
// because unshifted p overflowed fp16's 65504 ceiling — subexponential logit
// tails reach past 11 nats). satfinite pack = no-inf guarantee.
// V keeps hi/lo residual split (query-independent V quantization survives the
// mean pool — measured R6); fp16 split is tighter than the proven bf16 split.
__global__ __launch_bounds__(256) void k_attn_tc() {
    __shared__ __align__(16) char sraw[6 * TILEB];   // 36KB

    int h    = blockIdx.y;
    int q0   = blockIdx.x * TQ;
    int tid  = threadIdx.x;
    int warp = tid >> 5;
    int lane = tid & 31;
    int qw   = warp & 3;      // query sub-tile (16 rows)
    int half = warp >> 2;     // split-K half
    int lt   = tid & 127;     // thread index within half

    __half (*sK )[KPAD] = (__half (*)[KPAD])(sraw + half * 3 * TILEB + 0 * TILEB);
    __half (*sVh)[KPAD] = (__half (*)[KPAD])(sraw + half * 3 * TILEB + 1 * TILEB);
    __half (*sVl)[KPAD] = (__half (*)[KPAD])(sraw + half * 3 * TILEB + 2 * TILEB);

    // ---- stage Q tile (64 rows x 16 cols fp16) into first buffer ----
    {
        __half (*qS)[KPAD] = (__half (*)[KPAD])(sraw);
        if (tid < 128) {
            int row = tid >> 1, hf = tid & 1;
            *(uint4*)&qS[row][hf * 8] = *(const uint4*)(g_qf + (q0 + row) * HID + h * DH + hf * 8);
        }
        __syncthreads();
    }
    unsigned a[4];
    {
        __half (*qS)[KPAD] = (__half (*)[KPAD])(sraw);
        int mrow = qw * 16 + ((lane >> 3) & 1) * 8 + (lane & 7);
        unsigned coff = (lane >> 4) * 16;
        ldm_x4(a, scvt(&qS[mrow][0]) + coff);
    }
    __syncthreads();

    float o[8];
    #pragma unroll
    for (int i = 0; i < 8; i++) o[i] = 0.0f;
    float l0 = 0.0f, l1 = 0.0f;

    // per-lane x4 ldmatrix address components
    int krow = ((lane >> 4) & 1) * 8 + (lane & 7);        // K: key row within 16
    unsigned kcoff = ((lane >> 3) & 1) * 16;              // K: d half (bytes)
    int vrow = (lane & 7) + ((lane >> 3) & 1) * 8;        // V: key row within 16
    unsigned vcoff = ((lane >> 4) & 1) * 16;              // V: d half (bytes)
    int bar_id = 1 + half;

    for (int it = 0; it < 16; it++) {
        int kt = half * 16 + it;
        {
            int src = (kt * TK + lt) * HID + h * DH;
            const uint4* kf = (const uint4*)(g_kf + src);
            const uint4* vh = (const uint4*)(g_vhf + src);
            const uint4* vl = (const uint4*)(g_vlf + src);
            *(uint4*)&sK [lt][0] = kf[0]; *(uint4*)&sK [lt][8] = kf[1];
            *(uint4*)&sVh[lt][0] = vh[0]; *(uint4*)&sVh[lt][8] = vh[1];
            *(uint4*)&sVl[lt][0] = vl[0]; *(uint4*)&sVl[lt][8] = vl[1];
        }
        half_bar(bar_id);

        #pragma unroll
        for (int g16 = 0; g16 < TK / 16; g16++) {
            // QK: one x4 covers both 8-key groups x both d halves
            unsigned bk[4];
            ldm_x4(bk, scvt(&sK[g16 * 16 + krow][0]) + kcoff);
            float S[8];
            #pragma unroll
            for (int i = 0; i < 8; i++) S[i] = -SM_SHIFT;   // range shift rides in C operand
            mma16816f(S,     a, bk);      // keys 0-7
            mma16816f(S + 4, a, bk + 2);  // keys 8-15

            float p0 = ex2(S[0]), p1 = ex2(S[1]), p2 = ex2(S[2]), p3 = ex2(S[3]);
            float p4 = ex2(S[4]), p5 = ex2(S[5]), p6 = ex2(S[6]), p7 = ex2(S[7]);
            l0 += (p0 + p1) + (p4 + p5);   // D rows r0
            l1 += (p2 + p3) + (p6 + p7);   // D rows r0+8
            unsigned pa[4];
            pa[0] = cvt_f16x2(p0, p1);
            pa[1] = cvt_f16x2(p2, p3);
            pa[2] = cvt_f16x2(p4, p5);
            pa[3] = cvt_f16x2(p6, p7);

            // PV: one x4t per V array covers both d halves
            unsigned bvh[4], bvl[4];
            ldm_x4t(bvh, scvt(&sVh[g16 * 16 + vrow][0]) + vcoff);
            ldm_x4t(bvl, scvt(&sVl[g16 * 16 + vrow][0]) + vcoff);
            mma16816f(o,     pa, bvh);      // d 0-7
            mma16816f(o + 4, pa, bvh + 2);  // d 8-15
            mma16816f(o,     pa, bvl);
            mma16816f(o + 4, pa, bvl + 2);
        }
        half_bar(bar_id);
    }

    // ---- combine the two K-halves (smem overlay on dead tile buffers) ----
    __syncthreads();
    float* sO = (float*)sraw;
    if (half == 1) {
        float* dst = sO + (qw * 32 + lane) * 10;
        #pragma unroll
        for (int i = 0; i < 8; i++) dst[i] = o[i];
        dst[8] = l0; dst[9] = l1;
    }
    __syncthreads();
    if (half == 1) return;

    {
        const float* srcp = sO + (qw * 32 + lane) * 10;
        #pragma unroll
        for (int i = 0; i < 8; i++) o[i] += srcp[i];
        l0 += srcp[8]; l1 += srcp[9];
    }
    l0 += __shfl_xor_sync(0xFFFFFFFFu, l0, 1);
    l0 += __shfl_xor_sync(0xFFFFFFFFu, l0, 2);
    l1 += __shfl_xor_sync(0xFFFFFFFFu, l1, 1);
    l1 += __shfl_xor_sync(0xFFFFFFFFu, l1, 2);
    float inv0 = 1.0f / l0, inv1 = 1.0f / l1;

    int r0c = lane >> 2;
    int cc  = (lane & 3) * 2;
    int row0 = q0 + qw * 16 + r0c;
    int row1 = row0 + 8;
    float* d0 = g_av + row0 * HID + h * DH;
    float* d1 = g_av + row1 * HID + h * DH;
    d0[cc]     = o[0] * inv0;  d0[cc + 1] = o[1] * inv0;
    d1[cc]     = o[2] * inv1;  d1[cc + 1] = o[3] * inv1;
    d0[cc + 8] = o[4] * inv0;  d0[cc + 9] = o[5] * inv0;
    d1[cc + 8] = o[6] * inv1;  d1[cc + 9] = o[7] * inv1;
}

// ---------------- 13: column mean + (last block) Wo/MLP head ----------------
__global__ __launch_bounds__(256) void k_colsum_final(
    const float* __restrict__ Wo, const float* __restrict__ bo,
    const float* __restrict__ W1, const float* __restrict__ b1,
    const float* __restrict__ W2, const float* __restrict__ b2,
    float* __restrict__ out)
{
    __shared__ float sm[256];
    __shared__ int is_last;
    int col = blockIdx.x;
    int t = threadIdx.x;
    float s = 0.0f;
    for (int r = t; r < NSEL; r += 256) s += g_av[r * HID + col];
    sm[t] = s;
    __syncthreads();
    for (int o = 128; o > 0; o >>= 1) {
        if (t < o) sm[t] += sm[t + o];
        __syncthreads();
    }
    if (t == 0) {
        g_mav[col] = sm[0] * (1.0f / NSEL);
        __threadfence();
        is_last = (atomicAdd(&g_done, 1) == HID - 1);
    }
    __syncthreads();
    if (!is_last) return;

    __shared__ float mav[HID];
    __shared__ float pooled[HID];
    __shared__ float t1[OUTD];
    if (t < HID) mav[t] = g_mav[t];
    __syncthreads();
    if (t < HID) {
        float acc = bo[t];
        for (int d = 0; d < HID; d++) acc = fmaf(mav[d], Wo[d * HID + t], acc);
        pooled[t] = acc;
    }
    __syncthreads();
    {
        float acc = b1[t];
        for (int d = 0; d < HID; d++) acc = fmaf(pooled[d], W1[d * OUTD + t], acc);
        t1[t] = fmaxf(acc, 0.0f);
    }
    __syncthreads();
    {
        float acc = b2[t];
        for (int d = 0; d < OUTD; d++) acc = fmaf(t1[d], W2[d * OUTD + t], acc);
        out[t] = acc;
    }
}

// ---------------- launcher ----------------
extern "C" void kernel_launch(void* const* d_in, const int* in_sizes, int n_in,
                              void* d_out, int out_size)
{
    const float* x    = (const float*)d_in[0];
    const float* pos  = (const float*)d_in[1];
    const float* lig  = (const float*)d_in[2];
    const float* Wn   = (const float*)d_in[3];
    const float* bn   = (const float*)d_in[4];
    const float* Wq   = (const float*)d_in[5];
    const float* bq   = (const float*)d_in[6];
    const float* Wk   = (const float*)d_in[7];
    const float* bk   = (const float*)d_in[8];
    const float* Wv   = (const float*)d_in[9];
    const float* bv   = (const float*)d_in[10];
    const float* Wo   = (const float*)d_in[11];
    const float* bo   = (const float*)d_in[12];
    const float* W1   = (const float*)d_in[13];
    const float* b1   = (const float*)d_in[14];
    const float* W2   = (const float*)d_in[15];
    const float* b2   = (const float*)d_in[16];
    float* out = (float*)d_out;

    k_init<<<CBLK, 256>>>(lig, pos);
    k_cells<<<NATOMS / 256, 256>>>(pos);
    k_csum<<<CBLK, 256>>>();
    k_cstart<<<CBLK, 256>>>();
    k_scatter<<<NATOMS / 256, 256>>>(pos);
    k_neighbor<<<dim3(NATOMS / 256, 9), 256>>>(pos);
    k_scorekey<<<NATOMS / 256, 256>>>();
    k_scan<<<1, 1024>>>();
    k_boundary<<<NATOMS / 256, 256>>>();
    k_flags<<<NATOMS / 256, 256>>>();
    k_compact_all<<<64, 256>>>();
    k_qkv<<<NSEL / 16, 256>>>(x, Wn, bn, Wq, bq, Wk, bk, Wv, bv);
    k_attn_tc<<<dim3(NSEL / TQ, HEADS), 256>>>();
    k_colsum_final<<<HID, 256>>>(Wo, bo, W1, b1, W2, b2, out);
}

// round 15
// speedup vs baseline: 2.0685x; 1.2130x over previous
#include <cuda_runtime.h>
#include <cuda_bf16.h>
#include <cuda_fp16.h>
#include <stdint.h>

// ---------------- problem constants ----------------
#define NATOMS   16384
#define NSEL     4096
#define NODE_F   8
#define HID      128
#define HEADS    8
#define DH       16
#define OUTD     256
#define NLIG     32
#define NBINS    65536
#define NCHUNK   1024     // coarse chunks of 64 fine bins
#define CDIM     32       // spatial cells per axis (cell size 3.0, covers +/-48 = 4.8 sigma)
#define NCELLS   (CDIM * CDIM * CDIM)   // 32768
#define CBLK     (NCELLS / 256)         // 128 blocks over cells
#define IBLK     ((NBINS + NATOMS) / 256)  // 320 blocks for init

#define TQ 64      // queries per attention block (16 per warp-quad)
#define TK 128     // keys per smem tile
#define KPAD 24    // smem row stride in fp16 (48B: 16B-aligned, ldmatrix conflict-free)
#define TILEB (TK * KPAD * 2)   // 6144 bytes per tile array

// softmax range shift (log2 units): p = 2^(S - SHIFT). Shift cancels exactly in
// o/l; it moves P into fp16's representable range (proven R14).
#define SM_SHIFT 8.0f

typedef unsigned long long ull;

// ---------------- helpers ----------------
__device__ __forceinline__ unsigned scvt(const void* p) {
    return (unsigned)__cvta_generic_to_shared(p);
}
__device__ __forceinline__ void ldm_x4(unsigned* r, unsigned a) {
    asm volatile("ldmatrix.sync.aligned.m8n8.x4.shared.b16 {%0,%1,%2,%3}, [%4];"
        : "=r"(r[0]), "=r"(r[1]), "=r"(r[2]), "=r"(r[3]) : "r"(a));
}
__device__ __forceinline__ void ldm_x4t(unsigned* r, unsigned a) {
    asm volatile("ldmatrix.sync.aligned.m8n8.x4.trans.shared.b16 {%0,%1,%2,%3}, [%4];"
        : "=r"(r[0]), "=r"(r[1]), "=r"(r[2]), "=r"(r[3]) : "r"(a));
}
// fp16 MMA, fp32 accumulate
__device__ __forceinline__ void mma16816f(float* d, const unsigned* a, const unsigned* b) {
    asm volatile(
        "mma.sync.aligned.m16n8k16.row.col.f32.f16.f16.f32 "
        "{%0,%1,%2,%3}, {%4,%5,%6,%7}, {%8,%9}, {%0,%1,%2,%3};"
        : "+f"(d[0]), "+f"(d[1]), "+f"(d[2]), "+f"(d[3])
        : "r"(a[0]), "r"(a[1]), "r"(a[2]), "r"(a[3]), "r"(b[0]), "r"(b[1]));
}
// saturating pack: clamps instead of producing inf
__device__ __forceinline__ unsigned cvt_f16x2(float lo, float hi) {
    unsigned r;
    asm("cvt.rn.satfinite.f16x2.f32 %0, %1, %2;" : "=r"(r) : "f"(hi), "f"(lo));  // d.hi=%1
    return r;
}
// packed fp16 exp2: one MUFU op, two results, output ready for MMA
__device__ __forceinline__ unsigned h2ex2(unsigned x) {
    unsigned r; asm("ex2.approx.f16x2 %0, %1;" : "=r"(r) : "r"(x)); return r;
}
// named barrier over 128 threads (one split-K half)
__device__ __forceinline__ void half_bar(int id) {
    asm volatile("bar.sync %0, %1;" :: "r"(id), "r"(128) : "memory");
}

// ---------------- scratch (static device memory; no allocation) ----------------
__device__ float    g_sq[NATOMS];
__device__ float    g_s0[NATOMS];
__device__ int      g_cnt[NATOMS];
__device__ int      g_cell[NATOMS];
__device__ int      g_cellcnt[NCELLS];
__device__ int      g_cellstart[NCELLS + 1];
__device__ int      g_cellptr[NCELLS];
__device__ int      g_cblk[CBLK];
__device__ __align__(16) float4 g_cellpos[NATOMS];   // (x, y, z, -0.5*sq)
__device__ unsigned g_keys[NATOMS];
__device__ unsigned g_hist[NBINS];
__device__ unsigned g_chist[NCHUNK];
__device__ int      g_H;
__device__ int      g_r;
__device__ int      g_m;
__device__ int      g_done;
__device__ ull      g_bbuf[NATOMS];
__device__ int      g_sel[NATOMS];
__device__ int      g_idx[NSEL];
__device__ __align__(16) __half g_qf[NSEL * HID];   // q * scale*log2e (fp16)
__device__ __align__(16) __half g_kf[NSEL * HID];   // k (fp16)
__device__ __align__(16) __half g_vf[NSEL * HID];   // V (fp16 single: err ~2e-4 by calibrated model)
__device__ __align__(16) float g_av[NSEL * HID];
__device__ float    g_mav[HID];

// ---------------- 0: init (zero hist/chist/cellcnt/cnt + ligand center + base) ----------------
__global__ void k_init(const float* __restrict__ lig, const float* __restrict__ pos) {
    __shared__ float c3[3];
    int t = threadIdx.x;
    if (t < 32) {
        float x = lig[t * 3 + 0], y = lig[t * 3 + 1], z = lig[t * 3 + 2];
        #pragma unroll
        for (int o = 16; o > 0; o >>= 1) {
            x += __shfl_down_sync(0xFFFFFFFFu, x, o);
            y += __shfl_down_sync(0xFFFFFFFFu, y, o);
            z += __shfl_down_sync(0xFFFFFFFFu, z, o);
        }
        if (t == 0) {
            c3[0] = x * (1.0f / NLIG);
            c3[1] = y * (1.0f / NLIG);
            c3[2] = z * (1.0f / NLIG);
        }
    }
    __syncthreads();
    int gi = blockIdx.x * 256 + t;
    if (gi < NBINS) g_hist[gi] = 0;
    if (gi < NCHUNK) g_chist[gi] = 0;
    if (gi < NCELLS) g_cellcnt[gi] = 0;
    if (gi == 0) { g_m = 0; g_done = 0; }
    int ci = gi - NBINS;
    if (ci >= 0 && ci < NATOMS) g_cnt[ci] = 0;
    if (gi < NATOMS) {
        float x = pos[gi * 3 + 0], y = pos[gi * 3 + 1], z = pos[gi * 3 + 2];
        g_sq[gi] = fmaf(z, z, fmaf(y, y, x * x));
        float dx = x - c3[0], dy = y - c3[1], dz = z - c3[2];
        float d = sqrtf(fmaf(dz, dz, fmaf(dy, dy, dx * dx)));
        g_s0[gi] = 1.0f / (1.0f + d / 5.0f);
    }
}

// ---------------- 1: assign cells + count ----------------
__global__ void k_cells(const float* __restrict__ pos) {
    int i = blockIdx.x * 256 + threadIdx.x;
    if (i >= NATOMS) return;
    float x = pos[i * 3 + 0], y = pos[i * 3 + 1], z = pos[i * 3 + 2];
    int cx = min(max((int)floorf(x * (1.0f / 3.0f)) + 16, 0), CDIM - 1);
    int cy = min(max((int)floorf(y * (1.0f / 3.0f)) + 16, 0), CDIM - 1);
    int cz = min(max((int)floorf(z * (1.0f / 3.0f)) + 16, 0), CDIM - 1);
    int cell = (cz * CDIM + cy) * CDIM + cx;
    g_cell[i] = cell;
    atomicAdd(&g_cellcnt[cell], 1);
}

// ---------------- 2: per-block cell-count sums ----------------
__global__ __launch_bounds__(256) void k_csum() {
    __shared__ int sm[256];
    int t = threadIdx.x;
    sm[t] = g_cellcnt[blockIdx.x * 256 + t];
    __syncthreads();
    for (int o = 128; o > 0; o >>= 1) {
        if (t < o) sm[t] += sm[t + o];
        __syncthreads();
    }
    if (t == 0) g_cblk[blockIdx.x] = sm[0];
}

// ---------------- 3: cell starts ----------------
__global__ __launch_bounds__(256) void k_cstart() {
    __shared__ int sc[256];
    __shared__ int s_off;
    int t = threadIdx.x, b = blockIdx.x;
    int s = 0;
    for (int j = t; j < b; j += 256) s += g_cblk[j];
    sc[t] = s;
    __syncthreads();
    for (int o = 128; o > 0; o >>= 1) {
        if (t < o) sc[t] += sc[t + o];
        __syncthreads();
    }
    if (t == 0) s_off = sc[0];
    __syncthreads();
    int c = b * 256 + t;
    int cnt = g_cellcnt[c];
    sc[t] = cnt;
    __syncthreads();
    for (int o = 1; o < 256; o <<= 1) {
        int v = (t >= o) ? sc[t - o] : 0;
        __syncthreads();
        sc[t] += v;
        __syncthreads();
    }
    int start = s_off + sc[t] - cnt;   // exclusive prefix
    g_cellstart[c] = start;
    g_cellptr[c]   = start;
    if (b == 0 && t == 0) g_cellstart[NCELLS] = NATOMS;
}

// ---------------- 4: scatter atoms into cell-sorted packed array ----------------
__global__ void k_scatter(const float* __restrict__ pos) {
    int i = blockIdx.x * 256 + threadIdx.x;
    if (i >= NATOMS) return;
    int slot = atomicAdd(&g_cellptr[g_cell[i]], 1);
    g_cellpos[slot] = make_float4(pos[i * 3 + 0], pos[i * 3 + 1], pos[i * 3 + 2],
                                  -0.5f * g_sq[i]);
}

// ---------------- 5: neighbor counting via cells ----------------
__global__ __launch_bounds__(256) void k_neighbor(const float* __restrict__ pos) {
    int i = blockIdx.x * 256 + threadIdx.x;
    int s = blockIdx.y;                 // 0..8
    int dy = s % 3 - 1, dz = s / 3 - 1;
    float px = pos[i * 3 + 0], py = pos[i * 3 + 1], pz = pos[i * 3 + 2];
    float ci = 4.5f - 0.5f * g_sq[i];
    int cell = g_cell[i];
    int cx = cell % CDIM;
    int cy = (cell / CDIM) % CDIM;
    int cz = cell / (CDIM * CDIM);
    int ny = cy + dy, nz = cz + dz;
    int cnt = 0;
    if (ny >= 0 && ny < CDIM && nz >= 0 && nz < CDIM) {
        int rowbase = (nz * CDIM + ny) * CDIM;
        int lo = rowbase + max(cx - 1, 0);
        int hi = rowbase + min(cx + 1, CDIM - 1);
        int a = g_cellstart[lo];
        int b = g_cellstart[hi + 1];
        #pragma unroll 4
        for (int j = a; j < b; j++) {
            float4 q = g_cellpos[j];
            float v = fmaf(px, q.x, fmaf(py, q.y, fmaf(pz, q.z, q.w + ci)));
            cnt += (v > 0.0f);
        }
    }
    atomicAdd(&g_cnt[i], cnt);
}

// ---------------- 6: final scores -> sortable keys + fine & coarse histograms ----------------
__global__ void k_scorekey() {
    int i = blockIdx.x * blockDim.x + threadIdx.x;
    if (i >= NATOMS) return;
    float surface = 1.0f / (float)g_cnt[i];
    float s = g_s0[i] + 0.5f * surface;
    unsigned key = __float_as_uint(s);
    g_keys[i] = key;
    atomicAdd(&g_hist[key >> 16], 1u);
    atomicAdd(&g_chist[key >> 22], 1u);   // 64-bin chunk
}

// ---------------- 7: threshold bin — parallel over chunk hist ----------------
__global__ __launch_bounds__(1024) void k_scan() {
    __shared__ unsigned csum[NCHUNK];
    __shared__ unsigned hs[64];
    __shared__ int s_chunk;
    __shared__ unsigned s_above;
    int t = threadIdx.x;
    csum[t] = g_chist[t];
    __syncthreads();
    for (int o = 1; o < NCHUNK; o <<= 1) {
        unsigned v = (t + o < NCHUNK) ? csum[t + o] : 0u;
        __syncthreads();
        csum[t] += v;
        __syncthreads();
    }
    {
        unsigned mine = csum[t];
        unsigned nxt = (t + 1 < NCHUNK) ? csum[t + 1] : 0u;
        if (mine >= (unsigned)NSEL && nxt < (unsigned)NSEL) { s_chunk = t; s_above = nxt; }
    }
    __syncthreads();
    int chunk = s_chunk;
    unsigned above = s_above;
    if (t < 64) hs[t] = g_hist[chunk * 64 + t];
    __syncthreads();
    for (int o = 1; o < 64; o <<= 1) {
        unsigned v = (t < 64 && t + o < 64) ? hs[t + o] : 0u;
        __syncthreads();
        if (t < 64) hs[t] += v;
        __syncthreads();
    }
    if (t < 64) {
        unsigned mine = above + hs[t];
        unsigned nxt  = above + ((t + 1 < 64) ? hs[t + 1] : 0u);
        if (mine >= (unsigned)NSEL && nxt < (unsigned)NSEL) {
            g_H = chunk * 64 + t;
            g_r = (int)((unsigned)NSEL - nxt);
        }
    }
}

// ---------------- 8: boundary-bin elements ----------------
__global__ void k_boundary() {
    int i = blockIdx.x * blockDim.x + threadIdx.x;
    if (i >= NATOMS) return;
    unsigned key = g_keys[i];
    if ((int)(key >> 16) == g_H) {
        int p = atomicAdd(&g_m, 1);
        g_bbuf[p] = ((ull)key << 32) | (ull)(0xFFFFFFFFu - (unsigned)i);
    }
}

// ---------------- 9: selection flags ----------------
__global__ void k_flags() {
    int i = blockIdx.x * blockDim.x + threadIdx.x;
    if (i >= NATOMS) return;
    unsigned key = g_keys[i];
    int hi = (int)(key >> 16);
    int s = 0;
    if (hi > g_H) s = 1;
    else if (hi == g_H) {
        ull mine = ((ull)key << 32) | (ull)(0xFFFFFFFFu - (unsigned)i);
        int m = g_m, cnt = 0, r = g_r;
        for (int t = 0; t < m; t++) cnt += (g_bbuf[t] > mine);
        if (cnt < r) s = 1;
    }
    g_sel[i] = s;
}

// ---------------- 10: single-pass deterministic compaction ----------------
__global__ __launch_bounds__(256) void k_compact_all() {
    __shared__ int sc[256];
    __shared__ int s_off;
    int t = threadIdx.x, b = blockIdx.x;
    int pre = b * 256;
    int s = 0;
    for (int j = t; j < pre; j += 256) s += g_sel[j];
    sc[t] = s;
    __syncthreads();
    for (int o = 128; o > 0; o >>= 1) {
        if (t < o) sc[t] += sc[t + o];
        __syncthreads();
    }
    if (t == 0) s_off = sc[0];
    __syncthreads();
    int i = pre + t;
    int f = g_sel[i];
    sc[t] = f;
    __syncthreads();
    for (int o = 1; o < 256; o <<= 1) {
        int v = (t >= o) ? sc[t - o] : 0;
        __syncthreads();
        sc[t] += v;
        __syncthreads();
    }
    if (f) g_idx[s_off + sc[t] - 1] = i;
}

// ---------------- 11: gather + embed + QKV (fp16 outputs) ----------------
__global__ __launch_bounds__(256) void k_qkv(
    const float* __restrict__ x,
    const float* __restrict__ Wn, const float* __restrict__ bn,
    const float* __restrict__ Wq, const float* __restrict__ bq,
    const float* __restrict__ Wk, const float* __restrict__ bk,
    const float* __restrict__ Wv, const float* __restrict__ bv)
{
    __shared__ float hs[16][HID];
    int t = threadIdx.x;
    int c = t & 127;          // column
    int half = t >> 7;        // 0/1 -> rows 0-7 / 8-15
    int r0 = blockIdx.x * 16;
    #pragma unroll
    for (int k = 0; k < 8; k++) {
        int rr = half * 8 + k;
        int row = g_idx[r0 + rr];
        const float* xr = x + row * NODE_F;
        float acc = bn[c];
        #pragma unroll
        for (int f = 0; f < NODE_F; f++) acc = fmaf(__ldg(xr + f), Wn[f * HID + c], acc);
        hs[rr][c] = acc;
    }
    __syncthreads();
    float aq[8], ak[8], av[8];
    #pragma unroll
    for (int rr = 0; rr < 8; rr++) { aq[rr] = bq[c]; ak[rr] = bk[c]; av[rr] = bv[c]; }
    for (int d = 0; d < HID; d++) {
        float wq = Wq[d * HID + c], wk = Wk[d * HID + c], wv = Wv[d * HID + c];
        #pragma unroll
        for (int rr = 0; rr < 8; rr++) {
            float h = hs[half * 8 + rr][d];
            aq[rr] = fmaf(h, wq, aq[rr]);
            ak[rr] = fmaf(h, wk, ak[rr]);
            av[rr] = fmaf(h, wv, av[rr]);
        }
    }
    const float cs = 0.25f * 1.4426950408889634f;  // scale * log2(e), folded into Q
    #pragma unroll
    for (int rr = 0; rr < 8; rr++) {
        int o = (r0 + half * 8 + rr) * HID + c;
        g_qf[o] = __float2half_rn(aq[rr] * cs);
        g_kf[o] = __float2half_rn(ak[rr]);
        g_vf[o] = __float2half_rn(av[rr]);
    }
}

// ---------------- 12: tensor-core attention, fp16, intra-block split-K x2 ----------------
// S = Q·K (fp16, fp32 accum) init to -SM_SHIFT (range shift, proven R14).
// P = ex2.approx.f16x2(satfinite-f16(S)) — one MUFU per 2 values, no separate
// pack (same P precision as R14: fp16 ulp dominated either way).
// l = P·ones via one MMA (exact fp32 row sums, no shfl reduce needed).
// V single fp16: systematic error = measured bf16 (1.58e-3, R6) / 8 = ~2e-4.
__global__ __launch_bounds__(256) void k_attn_tc() {
    __shared__ __align__(16) char sraw[4 * TILEB];   // 24KB

    int h    = blockIdx.y;
    int q0   = blockIdx.x * TQ;
    int tid  = threadIdx.x;
    int warp = tid >> 5;
    int lane = tid & 31;
    int qw   = warp & 3;      // query sub-tile (16 rows)
    int half = warp >> 2;     // split-K half
    int lt   = tid & 127;     // thread index within half

    __half (*sK)[KPAD] = (__half (*)[KPAD])(sraw + half * 2 * TILEB + 0 * TILEB);
    __half (*sV)[KPAD] = (__half (*)[KPAD])(sraw + half * 2 * TILEB + 1 * TILEB);

    // ---- stage Q tile (64 rows x 16 cols fp16) into first buffer ----
    {
        __half (*qS)[KPAD] = (__half (*)[KPAD])(sraw);
        if (tid < 128) {
            int row = tid >> 1, hf = tid & 1;
            *(uint4*)&qS[row][hf * 8] = *(const uint4*)(g_qf + (q0 + row) * HID + h * DH + hf * 8);
        }
        __syncthreads();
    }
    unsigned a[4];
    {
        __half (*qS)[KPAD] = (__half (*)[KPAD])(sraw);
        int mrow = qw * 16 + ((lane >> 3) & 1) * 8 + (lane & 7);
        unsigned coff = (lane >> 4) * 16;
        ldm_x4(a, scvt(&qS[mrow][0]) + coff);
    }
    __syncthreads();

    float o[8];
    #pragma unroll
    for (int i = 0; i < 8; i++) o[i] = 0.0f;
    float L[4];
    #pragma unroll
    for (int i = 0; i < 4; i++) L[i] = 0.0f;
    const unsigned ONES2 = 0x3C003C00u;             // (1.0h, 1.0h)
    unsigned bones[2] = {ONES2, ONES2};

    // per-lane x4 ldmatrix address components
    int krow = ((lane >> 4) & 1) * 8 + (lane & 7);        // K: key row within 16
    unsigned kcoff = ((lane >> 3) & 1) * 16;              // K: d half (bytes)
    int vrow = (lane & 7) + ((lane >> 3) & 1) * 8;        // V: key row within 16
    unsigned vcoff = ((lane >> 4) & 1) * 16;              // V: d half (bytes)
    int bar_id = 1 + half;

    for (int it = 0; it < 16; it++) {
        int kt = half * 16 + it;
        {
            int src = (kt * TK + lt) * HID + h * DH;
            const uint4* kf = (const uint4*)(g_kf + src);
            const uint4* vf = (const uint4*)(g_vf + src);
            *(uint4*)&sK[lt][0] = kf[0]; *(uint4*)&sK[lt][8] = kf[1];
            *(uint4*)&sV[lt][0] = vf[0]; *(uint4*)&sV[lt][8] = vf[1];
        }
        half_bar(bar_id);

        #pragma unroll
        for (int g16 = 0; g16 < TK / 16; g16++) {
            // QK: one x4 covers both 8-key groups x both d halves
            unsigned bk[4];
            ldm_x4(bk, scvt(&sK[g16 * 16 + krow][0]) + kcoff);
            float S[8];
            #pragma unroll
            for (int i = 0; i < 8; i++) S[i] = -SM_SHIFT;   // range shift rides in C operand
            mma16816f(S,     a, bk);      // keys 0-7
            mma16816f(S + 4, a, bk + 2);  // keys 8-15

            // packed fp16 exp2: pack S (satfinite) then one MUFU per pair
            unsigned pa[4];
            pa[0] = h2ex2(cvt_f16x2(S[0], S[1]));
            pa[1] = h2ex2(cvt_f16x2(S[2], S[3]));
            pa[2] = h2ex2(cvt_f16x2(S[4], S[5]));
            pa[3] = h2ex2(cvt_f16x2(S[6], S[7]));

            // l += P * ones (exact fp32 row sums; all lanes in quad get full sum)
            mma16816f(L, pa, bones);

            // PV: one x4t covers both d halves
            unsigned bv[4];
            ldm_x4t(bv, scvt(&sV[g16 * 16 + vrow][0]) + vcoff);
            mma16816f(o,     pa, bv);      // d 0-7
            mma16816f(o + 4, pa, bv + 2);  // d 8-15
        }
        half_bar(bar_id);
    }

    // ---- combine the two K-halves (smem overlay on dead tile buffers) ----
    __syncthreads();
    float* sO = (float*)sraw;
    if (half == 1) {
        float* dst = sO + (qw * 32 + lane) * 10;
        #pragma unroll
        for (int i = 0; i < 8; i++) dst[i] = o[i];
        dst[8] = L[0]; dst[9] = L[2];
    }
    __syncthreads();
    if (half == 1) return;

    float l0, l1;
    {
        const float* srcp = sO + (qw * 32 + lane) * 10;
        #pragma unroll
        for (int i = 0; i < 8; i++) o[i] += srcp[i];
        l0 = L[0] + srcp[8];
        l1 = L[2] + srcp[9];
    }
    float inv0 = 1.0f / l0, inv1 = 1.0f / l1;

    int r0c = lane >> 2;
    int cc  = (lane & 3) * 2;
    int row0 = q0 + qw * 16 + r0c;
    int row1 = row0 + 8;
    float* d0 = g_av + row0 * HID + h * DH;
    float* d1 = g_av + row1 * HID + h * DH;
    d0[cc]     = o[0] * inv0;  d0[cc + 1] = o[1] * inv0;
    d1[cc]     = o[2] * inv1;  d1[cc + 1] = o[3] * inv1;
    d0[cc + 8] = o[4] * inv0;  d0[cc + 9] = o[5] * inv0;
    d1[cc + 8] = o[6] * inv1;  d1[cc + 9] = o[7] * inv1;
}

// ---------------- 13: column mean + (last block) Wo/MLP head ----------------
__global__ __launch_bounds__(256) void k_colsum_final(
    const float* __restrict__ Wo, const float* __restrict__ bo,
    const float* __restrict__ W1, const float* __restrict__ b1,
    const float* __restrict__ W2, const float* __restrict__ b2,
    float* __restrict__ out)
{
    __shared__ float sm[256];
    __shared__ int is_last;
    int col = blockIdx.x;
    int t = threadIdx.x;
    float s = 0.0f;
    for (int r = t; r < NSEL; r += 256) s += g_av[r * HID + col];
    sm[t] = s;
    __syncthreads();
    for (int o = 128; o > 0; o >>= 1) {
        if (t < o) sm[t] += sm[t + o];
        __syncthreads();
    }
    if (t == 0) {
        g_mav[col] = sm[0] * (1.0f / NSEL);
        __threadfence();
        is_last = (atomicAdd(&g_done, 1) == HID - 1);
    }
    __syncthreads();
    if (!is_last) return;

    __shared__ float mav[HID];
    __shared__ float pooled[HID];
    __shared__ float t1[OUTD];
    if (t < HID) mav[t] = g_mav[t];
    __syncthreads();
    if (t < HID) {
        float acc = bo[t];
        for (int d = 0; d < HID; d++) acc = fmaf(mav[d], Wo[d * HID + t], acc);
        pooled[t] = acc;
    }
    __syncthreads();
    {
        float acc = b1[t];
        for (int d = 0; d < HID; d++) acc = fmaf(pooled[d], W1[d * OUTD + t], acc);
        t1[t] = fmaxf(acc, 0.0f);
    }
    __syncthreads();
    {
        float acc = b2[t];
        for (int d = 0; d < OUTD; d++) acc = fmaf(t1[d], W2[d * OUTD + t], acc);
        out[t] = acc;
    }
}

// ---------------- launcher ----------------
extern "C" void kernel_launch(void* const* d_in, const int* in_sizes, int n_in,
                              void* d_out, int out_size)
{
    const float* x    = (const float*)d_in[0];
    const float* pos  = (const float*)d_in[1];
    const float* lig  = (const float*)d_in[2];
    const float* Wn   = (const float*)d_in[3];
    const float* bn   = (const float*)d_in[4];
    const float* Wq   = (const float*)d_in[5];
    const float* bq   = (const float*)d_in[6];
    const float* Wk   = (const float*)d_in[7];
    const float* bk   = (const float*)d_in[8];
    const float* Wv   = (const float*)d_in[9];
    const float* bv   = (const float*)d_in[10];
    const float* Wo   = (const float*)d_in[11];
    const float* bo   = (const float*)d_in[12];
    const float* W1   = (const float*)d_in[13];
    const float* b1   = (const float*)d_in[14];
    const float* W2   = (const float*)d_in[15];
    const float* b2   = (const float*)d_in[16];
    float* out = (float*)d_out;

    k_init<<<IBLK, 256>>>(lig, pos);
    k_cells<<<NATOMS / 256, 256>>>(pos);
    k_csum<<<CBLK, 256>>>();
    k_cstart<<<CBLK, 256>>>();
    k_scatter<<<NATOMS / 256, 256>>>(pos);
    k_neighbor<<<dim3(NATOMS / 256, 9), 256>>>(pos);
    k_scorekey<<<NATOMS / 256, 256>>>();
    k_scan<<<1, 1024>>>();
    k_boundary<<<NATOMS / 256, 256>>>();
    k_flags<<<NATOMS / 256, 256>>>();
    k_compact_all<<<64, 256>>>();
    k_qkv<<<NSEL / 16, 256>>>(x, Wn, bn, Wq, bq, Wk, bk, Wv, bv);
    k_attn_tc<<<dim3(NSEL / TQ, HEADS), 256>>>();
    k_colsum_final<<<HID, 256>>>(Wo, bo, W1, b1, W2, b2, out);
}

// round 16
// speedup vs baseline: 2.4543x; 1.1865x over previous
#include <cuda_runtime.h>
#include <cuda_bf16.h>
#include <cuda_fp16.h>
#include <stdint.h>

// ---------------- problem constants ----------------
#define NATOMS   16384
#define NSEL     4096
#define NODE_F   8
#define HID      128
#define HEADS    8
#define DH       16
#define OUTD     256
#define NLIG     32
#define NBINS    65536
#define NCHUNK   1024     // coarse chunks of 64 fine bins
#define CDIM     32       // spatial cells per axis (cell size 3.0)
#define NCELLS   (CDIM * CDIM * CDIM)   // 32768
#define CBLK     (NCELLS / 256)         // 128 blocks over cells
#define IBLK     ((NBINS + NATOMS) / 256)  // 320 blocks for init

#define TQ 128     // queries per attention block (32 per warp-quad)
#define TK 128     // keys per smem tile
#define KPAD 24    // smem row stride in fp16 (48B: 16B-aligned, ldmatrix conflict-free)
#define TILEB (TK * KPAD * 2)   // 6144 bytes per tile array

// softmax range shift (log2 units): p = 2^(S - SHIFT); cancels exactly in o/l.
#define SM_SHIFT 8.0f

typedef unsigned long long ull;

// ---------------- helpers ----------------
__device__ __forceinline__ unsigned scvt(const void* p) {
    return (unsigned)__cvta_generic_to_shared(p);
}
__device__ __forceinline__ void ldm_x4(unsigned* r, unsigned a) {
    asm volatile("ldmatrix.sync.aligned.m8n8.x4.shared.b16 {%0,%1,%2,%3}, [%4];"
        : "=r"(r[0]), "=r"(r[1]), "=r"(r[2]), "=r"(r[3]) : "r"(a));
}
__device__ __forceinline__ void ldm_x4t(unsigned* r, unsigned a) {
    asm volatile("ldmatrix.sync.aligned.m8n8.x4.trans.shared.b16 {%0,%1,%2,%3}, [%4];"
        : "=r"(r[0]), "=r"(r[1]), "=r"(r[2]), "=r"(r[3]) : "r"(a));
}
__device__ __forceinline__ void mma16816f(float* d, const unsigned* a, const unsigned* b) {
    asm volatile(
        "mma.sync.aligned.m16n8k16.row.col.f32.f16.f16.f32 "
        "{%0,%1,%2,%3}, {%4,%5,%6,%7}, {%8,%9}, {%0,%1,%2,%3};"
        : "+f"(d[0]), "+f"(d[1]), "+f"(d[2]), "+f"(d[3])
        : "r"(a[0]), "r"(a[1]), "r"(a[2]), "r"(a[3]), "r"(b[0]), "r"(b[1]));
}
__device__ __forceinline__ unsigned cvt_f16x2(float lo, float hi) {
    unsigned r;
    asm("cvt.rn.satfinite.f16x2.f32 %0, %1, %2;" : "=r"(r) : "f"(hi), "f"(lo));
    return r;
}
__device__ __forceinline__ unsigned h2ex2(unsigned x) {
    unsigned r; asm("ex2.approx.f16x2 %0, %1;" : "=r"(r) : "r"(x)); return r;
}
__device__ __forceinline__ void half_bar(int id) {
    asm volatile("bar.sync %0, %1;" :: "r"(id), "r"(128) : "memory");
}

// ---------------- scratch (static device memory; no allocation) ----------------
__device__ float    g_sq[NATOMS];
__device__ float    g_s0[NATOMS];
__device__ int      g_cnt[NATOMS];
__device__ int      g_cell[NATOMS];
__device__ int      g_cellcnt[NCELLS];
__device__ int      g_cellstart[NCELLS + 1];
__device__ int      g_cellptr[NCELLS];
__device__ __align__(16) float4 g_cellpos[NATOMS];   // (x, y, z, -0.5*sq)
__device__ unsigned g_keys[NATOMS];
__device__ unsigned g_hist[NBINS];
__device__ unsigned g_chist[NCHUNK];
__device__ int      g_H;
__device__ int      g_r;
__device__ int      g_m;
__device__ int      g_done;
__device__ ull      g_bbuf[NATOMS];
__device__ int      g_sel[NATOMS];
__device__ int      g_idx[NSEL];
__device__ __align__(16) __half g_qf[NSEL * HID];   // q * scale*log2e (fp16)
__device__ __align__(16) __half g_kf[NSEL * HID];   // k (fp16)
__device__ __align__(16) __half g_vf[NSEL * HID];   // V (fp16)
__device__ __align__(16) float g_av[NSEL * HID];
__device__ float    g_mav[HID];

// ---------------- 0: init ----------------
__global__ void k_init(const float* __restrict__ lig, const float* __restrict__ pos) {
    __shared__ float c3[3];
    int t = threadIdx.x;
    if (t < 32) {
        float x = lig[t * 3 + 0], y = lig[t * 3 + 1], z = lig[t * 3 + 2];
        #pragma unroll
        for (int o = 16; o > 0; o >>= 1) {
            x += __shfl_down_sync(0xFFFFFFFFu, x, o);
            y += __shfl_down_sync(0xFFFFFFFFu, y, o);
            z += __shfl_down_sync(0xFFFFFFFFu, z, o);
        }
        if (t == 0) {
            c3[0] = x * (1.0f / NLIG);
            c3[1] = y * (1.0f / NLIG);
            c3[2] = z * (1.0f / NLIG);
        }
    }
    __syncthreads();
    int gi = blockIdx.x * 256 + t;
    if (gi < NBINS) g_hist[gi] = 0;
    if (gi < NCHUNK) g_chist[gi] = 0;
    if (gi < NCELLS) g_cellcnt[gi] = 0;
    if (gi == 0) { g_m = 0; g_done = 0; }
    int ci = gi - NBINS;
    if (ci >= 0 && ci < NATOMS) g_cnt[ci] = 0;
    if (gi < NATOMS) {
        float x = pos[gi * 3 + 0], y = pos[gi * 3 + 1], z = pos[gi * 3 + 2];
        g_sq[gi] = fmaf(z, z, fmaf(y, y, x * x));
        float dx = x - c3[0], dy = y - c3[1], dz = z - c3[2];
        float d = sqrtf(fmaf(dz, dz, fmaf(dy, dy, dx * dx)));
        g_s0[gi] = 1.0f / (1.0f + d / 5.0f);
    }
}

// ---------------- 1: assign cells + count ----------------
__global__ void k_cells(const float* __restrict__ pos) {
    int i = blockIdx.x * 256 + threadIdx.x;
    if (i >= NATOMS) return;
    float x = pos[i * 3 + 0], y = pos[i * 3 + 1], z = pos[i * 3 + 2];
    int cx = min(max((int)floorf(x * (1.0f / 3.0f)) + 16, 0), CDIM - 1);
    int cy = min(max((int)floorf(y * (1.0f / 3.0f)) + 16, 0), CDIM - 1);
    int cz = min(max((int)floorf(z * (1.0f / 3.0f)) + 16, 0), CDIM - 1);
    int cell = (cz * CDIM + cy) * CDIM + cx;
    g_cell[i] = cell;
    atomicAdd(&g_cellcnt[cell], 1);
}

// ---------------- 2: cell starts (direct re-sum + shuffle scans, no k_csum) ----------------
__global__ __launch_bounds__(256) void k_cstart() {
    __shared__ int wsum[8];
    __shared__ int wpre[8];
    int t = threadIdx.x, b = blockIdx.x;
    int lane = t & 31, wid = t >> 5;

    // base offset: sum of cellcnt before this block's 256 cells
    int s = 0;
    for (int j = t; j < b * 256; j += 256) s += g_cellcnt[j];
    #pragma unroll
    for (int o = 16; o > 0; o >>= 1) s += __shfl_down_sync(0xFFFFFFFFu, s, o);
    if (lane == 0) wsum[wid] = s;
    __syncthreads();
    int s_off = 0;
    {
        int v = (lane < 8) ? wsum[lane] : 0;
        #pragma unroll
        for (int o = 4; o > 0; o >>= 1) v += __shfl_down_sync(0xFFFFFFFFu, v, o);
        s_off = __shfl_sync(0xFFFFFFFFu, v, 0);
    }

    // local inclusive scan of this block's 256 cell counts (warp shfl scan)
    int c = b * 256 + t;
    int cnt = g_cellcnt[c];
    int inc = cnt;
    #pragma unroll
    for (int o = 1; o < 32; o <<= 1) {
        int v = __shfl_up_sync(0xFFFFFFFFu, inc, o);
        if (lane >= o) inc += v;
    }
    if (lane == 31) wpre[wid] = inc;
    __syncthreads();
    int wbase = 0;
    #pragma unroll
    for (int w = 0; w < 8; w++) wbase += (w < wid) ? wpre[w] : 0;

    int start = s_off + wbase + inc - cnt;   // exclusive prefix
    g_cellstart[c] = start;
    g_cellptr[c]   = start;
    if (b == 0 && t == 0) g_cellstart[NCELLS] = NATOMS;
}

// ---------------- 3: scatter atoms into cell-sorted packed array ----------------
__global__ void k_scatter(const float* __restrict__ pos) {
    int i = blockIdx.x * 256 + threadIdx.x;
    if (i >= NATOMS) return;
    int slot = atomicAdd(&g_cellptr[g_cell[i]], 1);
    g_cellpos[slot] = make_float4(pos[i * 3 + 0], pos[i * 3 + 1], pos[i * 3 + 2],
                                  -0.5f * g_sq[i]);
}

// ---------------- 4: neighbor counting via cells ----------------
__global__ __launch_bounds__(256) void k_neighbor(const float* __restrict__ pos) {
    int i = blockIdx.x * 256 + threadIdx.x;
    int s = blockIdx.y;                 // 0..8
    int dy = s % 3 - 1, dz = s / 3 - 1;
    float px = pos[i * 3 + 0], py = pos[i * 3 + 1], pz = pos[i * 3 + 2];
    float ci = 4.5f - 0.5f * g_sq[i];
    int cell = g_cell[i];
    int cx = cell % CDIM;
    int cy = (cell / CDIM) % CDIM;
    int cz = cell / (CDIM * CDIM);
    int ny = cy + dy, nz = cz + dz;
    int cnt = 0;
    if (ny >= 0 && ny < CDIM && nz >= 0 && nz < CDIM) {
        int rowbase = (nz * CDIM + ny) * CDIM;
        int lo = rowbase + max(cx - 1, 0);
        int hi = rowbase + min(cx + 1, CDIM - 1);
        int a = g_cellstart[lo];
        int b = g_cellstart[hi + 1];
        #pragma unroll 4
        for (int j = a; j < b; j++) {
            float4 q = g_cellpos[j];
            float v = fmaf(px, q.x, fmaf(py, q.y, fmaf(pz, q.z, q.w + ci)));
            cnt += (v > 0.0f);
        }
    }
    atomicAdd(&g_cnt[i], cnt);
}

// ---------------- 5: scores -> keys + histograms ----------------
__global__ void k_scorekey() {
    int i = blockIdx.x * blockDim.x + threadIdx.x;
    if (i >= NATOMS) return;
    float surface = 1.0f / (float)g_cnt[i];
    float s = g_s0[i] + 0.5f * surface;
    unsigned key = __float_as_uint(s);
    g_keys[i] = key;
    atomicAdd(&g_hist[key >> 16], 1u);
    atomicAdd(&g_chist[key >> 22], 1u);
}

// ---------------- 6: threshold bin ----------------
__global__ __launch_bounds__(1024) void k_scan() {
    __shared__ unsigned csum[NCHUNK];
    __shared__ unsigned hs[64];
    __shared__ int s_chunk;
    __shared__ unsigned s_above;
    int t = threadIdx.x;
    csum[t] = g_chist[t];
    __syncthreads();
    for (int o = 1; o < NCHUNK; o <<= 1) {
        unsigned v = (t + o < NCHUNK) ? csum[t + o] : 0u;
        __syncthreads();
        csum[t] += v;
        __syncthreads();
    }
    {
        unsigned mine = csum[t];
        unsigned nxt = (t + 1 < NCHUNK) ? csum[t + 1] : 0u;
        if (mine >= (unsigned)NSEL && nxt < (unsigned)NSEL) { s_chunk = t; s_above = nxt; }
    }
    __syncthreads();
    int chunk = s_chunk;
    unsigned above = s_above;
    if (t < 64) hs[t] = g_hist[chunk * 64 + t];
    __syncthreads();
    for (int o = 1; o < 64; o <<= 1) {
        unsigned v = (t < 64 && t + o < 64) ? hs[t + o] : 0u;
        __syncthreads();
        if (t < 64) hs[t] += v;
        __syncthreads();
    }
    if (t < 64) {
        unsigned mine = above + hs[t];
        unsigned nxt  = above + ((t + 1 < 64) ? hs[t + 1] : 0u);
        if (mine >= (unsigned)NSEL && nxt < (unsigned)NSEL) {
            g_H = chunk * 64 + t;
            g_r = (int)((unsigned)NSEL - nxt);
        }
    }
}

// ---------------- 7: boundary-bin elements ----------------
__global__ void k_boundary() {
    int i = blockIdx.x * blockDim.x + threadIdx.x;
    if (i >= NATOMS) return;
    unsigned key = g_keys[i];
    if ((int)(key >> 16) == g_H) {
        int p = atomicAdd(&g_m, 1);
        g_bbuf[p] = ((ull)key << 32) | (ull)(0xFFFFFFFFu - (unsigned)i);
    }
}

// ---------------- 8: selection flags ----------------
__global__ void k_flags() {
    int i = blockIdx.x * blockDim.x + threadIdx.x;
    if (i >= NATOMS) return;
    unsigned key = g_keys[i];
    int hi = (int)(key >> 16);
    int s = 0;
    if (hi > g_H) s = 1;
    else if (hi == g_H) {
        ull mine = ((ull)key << 32) | (ull)(0xFFFFFFFFu - (unsigned)i);
        int m = g_m, cnt = 0, r = g_r;
        for (int t = 0; t < m; t++) cnt += (g_bbuf[t] > mine);
        if (cnt < r) s = 1;
    }
    g_sel[i] = s;
}

// ---------------- 9: single-pass deterministic compaction ----------------
__global__ __launch_bounds__(256) void k_compact_all() {
    __shared__ int sc[256];
    __shared__ int s_off;
    int t = threadIdx.x, b = blockIdx.x;
    int pre = b * 256;
    int s = 0;
    for (int j = t; j < pre; j += 256) s += g_sel[j];
    sc[t] = s;
    __syncthreads();
    for (int o = 128; o > 0; o >>= 1) {
        if (t < o) sc[t] += sc[t + o];
        __syncthreads();
    }
    if (t == 0) s_off = sc[0];
    __syncthreads();
    int i = pre + t;
    int f = g_sel[i];
    sc[t] = f;
    __syncthreads();
    for (int o = 1; o < 256; o <<= 1) {
        int v = (t >= o) ? sc[t - o] : 0;
        __syncthreads();
        sc[t] += v;
        __syncthreads();
    }
    if (f) g_idx[s_off + sc[t] - 1] = i;
}

// ---------------- 10: gather + embed + QKV (fp16 outputs) ----------------
__global__ __launch_bounds__(256) void k_qkv(
    const float* __restrict__ x,
    const float* __restrict__ Wn, const float* __restrict__ bn,
    const float* __restrict__ Wq, const float* __restrict__ bq,
    const float* __restrict__ Wk, const float* __restrict__ bk,
    const float* __restrict__ Wv, const float* __restrict__ bv)
{
    __shared__ float hs[16][HID];
    int t = threadIdx.x;
    int c = t & 127;
    int half = t >> 7;
    int r0 = blockIdx.x * 16;
    #pragma unroll
    for (int k = 0; k < 8; k++) {
        int rr = half * 8 + k;
        int row = g_idx[r0 + rr];
        const float* xr = x + row * NODE_F;
        float acc = bn[c];
        #pragma unroll
        for (int f = 0; f < NODE_F; f++) acc = fmaf(__ldg(xr + f), Wn[f * HID + c], acc);
        hs[rr][c] = acc;
    }
    __syncthreads();
    float aq[8], ak[8], av[8];
    #pragma unroll
    for (int rr = 0; rr < 8; rr++) { aq[rr] = bq[c]; ak[rr] = bk[c]; av[rr] = bv[c]; }
    for (int d = 0; d < HID; d++) {
        float wq = Wq[d * HID + c], wk = Wk[d * HID + c], wv = Wv[d * HID + c];
        #pragma unroll
        for (int rr = 0; rr < 8; rr++) {
            float h = hs[half * 8 + rr][d];
            aq[rr] = fmaf(h, wq, aq[rr]);
            ak[rr] = fmaf(h, wk, ak[rr]);
            av[rr] = fmaf(h, wv, av[rr]);
        }
    }
    const float cs = 0.25f * 1.4426950408889634f;
    #pragma unroll
    for (int rr = 0; rr < 8; rr++) {
        int o = (r0 + half * 8 + rr) * HID + c;
        g_qf[o] = __float2half_rn(aq[rr] * cs);
        g_kf[o] = __float2half_rn(ak[rr]);
        g_vf[o] = __float2half_rn(av[rr]);
    }
}

// ---------------- 11: tensor-core attention, fp16, TQ=128, split-K x2 ----------------
// Same numerics as the proven R15 kernel (fp16 QK, shifted f16x2 ex2, L via
// ones-MMA, fp16 V). TQ doubled to 128: each warp owns 32 query rows via two
// A-fragments — halves K/V L2 traffic (32 q-blocks instead of 64).
__global__ __launch_bounds__(256) void k_attn_tc() {
    __shared__ __align__(16) char sraw[4 * TILEB];   // 24KB

    int h    = blockIdx.y;
    int q0   = blockIdx.x * TQ;
    int tid  = threadIdx.x;
    int warp = tid >> 5;
    int lane = tid & 31;
    int qw   = warp & 3;      // query sub-tile (32 rows)
    int half = warp >> 2;     // split-K half
    int lt   = tid & 127;

    __half (*sK)[KPAD] = (__half (*)[KPAD])(sraw + half * 2 * TILEB + 0 * TILEB);
    __half (*sV)[KPAD] = (__half (*)[KPAD])(sraw + half * 2 * TILEB + 1 * TILEB);

    // ---- stage Q tile (128 rows x 16 cols fp16) into first buffer (6144B) ----
    {
        __half (*qS)[KPAD] = (__half (*)[KPAD])(sraw);
        int row = tid >> 1, hf = tid & 1;
        *(uint4*)&qS[row][hf * 8] = *(const uint4*)(g_qf + (q0 + row) * HID + h * DH + hf * 8);
        __syncthreads();
    }
    unsigned a0[4], a1[4];
    {
        __half (*qS)[KPAD] = (__half (*)[KPAD])(sraw);
        int mrow = qw * 32 + ((lane >> 3) & 1) * 8 + (lane & 7);
        unsigned coff = (lane >> 4) * 16;
        ldm_x4(a0, scvt(&qS[mrow][0]) + coff);
        ldm_x4(a1, scvt(&qS[mrow + 16][0]) + coff);
    }
    __syncthreads();

    float o0[8], o1[8];
    #pragma unroll
    for (int i = 0; i < 8; i++) { o0[i] = 0.0f; o1[i] = 0.0f; }
    float L0[4], L1[4];
    #pragma unroll
    for (int i = 0; i < 4; i++) { L0[i] = 0.0f; L1[i] = 0.0f; }
    const unsigned ONES2 = 0x3C003C00u;
    unsigned bones[2] = {ONES2, ONES2};

    int krow = ((lane >> 4) & 1) * 8 + (lane & 7);
    unsigned kcoff = ((lane >> 3) & 1) * 16;
    int vrow = (lane & 7) + ((lane >> 3) & 1) * 8;
    unsigned vcoff = ((lane >> 4) & 1) * 16;
    int bar_id = 1 + half;

    for (int it = 0; it < 16; it++) {
        int kt = half * 16 + it;
        {
            int src = (kt * TK + lt) * HID + h * DH;
            const uint4* kf = (const uint4*)(g_kf + src);
            const uint4* vf = (const uint4*)(g_vf + src);
            *(uint4*)&sK[lt][0] = kf[0]; *(uint4*)&sK[lt][8] = kf[1];
            *(uint4*)&sV[lt][0] = vf[0]; *(uint4*)&sV[lt][8] = vf[1];
        }
        half_bar(bar_id);

        #pragma unroll
        for (int g16 = 0; g16 < TK / 16; g16++) {
            unsigned bk[4];
            ldm_x4(bk, scvt(&sK[g16 * 16 + krow][0]) + kcoff);
            float S0[8], S1[8];
            #pragma unroll
            for (int i = 0; i < 8; i++) { S0[i] = -SM_SHIFT; S1[i] = -SM_SHIFT; }
            mma16816f(S0,     a0, bk);
            mma16816f(S0 + 4, a0, bk + 2);
            mma16816f(S1,     a1, bk);
            mma16816f(S1 + 4, a1, bk + 2);

            unsigned pa0[4], pa1[4];
            pa0[0] = h2ex2(cvt_f16x2(S0[0], S0[1]));
            pa0[1] = h2ex2(cvt_f16x2(S0[2], S0[3]));
            pa0[2] = h2ex2(cvt_f16x2(S0[4], S0[5]));
            pa0[3] = h2ex2(cvt_f16x2(S0[6], S0[7]));
            pa1[0] = h2ex2(cvt_f16x2(S1[0], S1[1]));
            pa1[1] = h2ex2(cvt_f16x2(S1[2], S1[3]));
            pa1[2] = h2ex2(cvt_f16x2(S1[4], S1[5]));
            pa1[3] = h2ex2(cvt_f16x2(S1[6], S1[7]));

            mma16816f(L0, pa0, bones);
            mma16816f(L1, pa1, bones);

            unsigned bv[4];
            ldm_x4t(bv, scvt(&sV[g16 * 16 + vrow][0]) + vcoff);
            mma16816f(o0,     pa0, bv);
            mma16816f(o0 + 4, pa0, bv + 2);
            mma16816f(o1,     pa1, bv);
            mma16816f(o1 + 4, pa1, bv + 2);
        }
        half_bar(bar_id);
    }

    // ---- combine the two K-halves (smem overlay on dead tile buffers) ----
    __syncthreads();
    float* sO = (float*)sraw;   // 4*32*20 floats = 10KB < 24KB
    if (half == 1) {
        float* dst = sO + (qw * 32 + lane) * 20;
        #pragma unroll
        for (int i = 0; i < 8; i++) { dst[i] = o0[i]; dst[8 + i] = o1[i]; }
        dst[16] = L0[0]; dst[17] = L0[2]; dst[18] = L1[0]; dst[19] = L1[2];
    }
    __syncthreads();
    if (half == 1) return;

    float l0, l1, l2, l3;
    {
        const float* srcp = sO + (qw * 32 + lane) * 20;
        #pragma unroll
        for (int i = 0; i < 8; i++) { o0[i] += srcp[i]; o1[i] += srcp[8 + i]; }
        l0 = L0[0] + srcp[16];
        l1 = L0[2] + srcp[17];
        l2 = L1[0] + srcp[18];
        l3 = L1[2] + srcp[19];
    }
    float inv0 = 1.0f / l0, inv1 = 1.0f / l1, inv2 = 1.0f / l2, inv3 = 1.0f / l3;

    int r0c = lane >> 2;
    int cc  = (lane & 3) * 2;
    int row0 = q0 + qw * 32 + r0c;
    float* d0 = g_av + row0 * HID + h * DH;            // rows +0
    float* d1 = g_av + (row0 + 8) * HID + h * DH;      // rows +8
    float* d2 = g_av + (row0 + 16) * HID + h * DH;     // rows +16
    float* d3 = g_av + (row0 + 24) * HID + h * DH;     // rows +24
    d0[cc]     = o0[0] * inv0;  d0[cc + 1] = o0[1] * inv0;
    d1[cc]     = o0[2] * inv1;  d1[cc + 1] = o0[3] * inv1;
    d0[cc + 8] = o0[4] * inv0;  d0[cc + 9] = o0[5] * inv0;
    d1[cc + 8] = o0[6] * inv1;  d1[cc + 9] = o0[7] * inv1;
    d2[cc]     = o1[0] * inv2;  d2[cc + 1] = o1[1] * inv2;
    d3[cc]     = o1[2] * inv3;  d3[cc + 1] = o1[3] * inv3;
    d2[cc + 8] = o1[4] * inv2;  d2[cc + 9] = o1[5] * inv2;
    d3[cc + 8] = o1[6] * inv3;  d3[cc + 9] = o1[7] * inv3;
}

// ---------------- 12: column mean + (last block) Wo/MLP head ----------------
__global__ __launch_bounds__(256) void k_colsum_final(
    const float* __restrict__ Wo, const float* __restrict__ bo,
    const float* __restrict__ W1, const float* __restrict__ b1,
    const float* __restrict__ W2, const float* __restrict__ b2,
    float* __restrict__ out)
{
    __shared__ float sm[256];
    __shared__ int is_last;
    int col = blockIdx.x;
    int t = threadIdx.x;
    float s = 0.0f;
    for (int r = t; r < NSEL; r += 256) s += g_av[r * HID + col];
    sm[t] = s;
    __syncthreads();
    for (int o = 128; o > 0; o >>= 1) {
        if (t < o) sm[t] += sm[t + o];
        __syncthreads();
    }
    if (t == 0) {
        g_mav[col] = sm[0] * (1.0f / NSEL);
        __threadfence();
        is_last = (atomicAdd(&g_done, 1) == HID - 1);
    }
    __syncthreads();
    if (!is_last) return;

    __shared__ float mav[HID];
    __shared__ float pooled[HID];
    __shared__ float t1[OUTD];
    if (t < HID) mav[t] = g_mav[t];
    __syncthreads();
    if (t < HID) {
        float acc = bo[t];
        for (int d = 0; d < HID; d++) acc = fmaf(mav[d], Wo[d * HID + t], acc);
        pooled[t] = acc;
    }
    __syncthreads();
    {
        float acc = b1[t];
        for (int d = 0; d < HID; d++) acc = fmaf(pooled[d], W1[d * OUTD + t], acc);
        t1[t] = fmaxf(acc, 0.0f);
    }
    __syncthreads();
    {
        float acc = b2[t];
        for (int d = 0; d < OUTD; d++) acc = fmaf(t1[d], W2[d * OUTD + t], acc);
        out[t] = acc;
    }
}

// ---------------- launcher ----------------
extern "C" void kernel_launch(void* const* d_in, const int* in_sizes, int n_in,
                              void* d_out, int out_size)
{
    const float* x    = (const float*)d_in[0];
    const float* pos  = (const float*)d_in[1];
    const float* lig  = (const float*)d_in[2];
    const float* Wn   = (const float*)d_in[3];
    const float* bn   = (const float*)d_in[4];
    const float* Wq   = (const float*)d_in[5];
    const float* bq   = (const float*)d_in[6];
    const float* Wk   = (const float*)d_in[7];
    const float* bk   = (const float*)d_in[8];
    const float* Wv   = (const float*)d_in[9];
    const float* bv   = (const float*)d_in[10];
    const float* Wo   = (const float*)d_in[11];
    const float* bo   = (const float*)d_in[12];
    const float* W1   = (const float*)d_in[13];
    const float* b1   = (const float*)d_in[14];
    const float* W2   = (const float*)d_in[15];
    const float* b2   = (const float*)d_in[16];
    float* out = (float*)d_out;

    k_init<<<IBLK, 256>>>(lig, pos);
    k_cells<<<NATOMS / 256, 256>>>(pos);
    k_cstart<<<CBLK, 256>>>();
    k_scatter<<<NATOMS / 256, 256>>>(pos);
    k_neighbor<<<dim3(NATOMS / 256, 9), 256>>>(pos);
    k_scorekey<<<NATOMS / 256, 256>>>();
    k_scan<<<1, 1024>>>();
    k_boundary<<<NATOMS / 256, 256>>>();
    k_flags<<<NATOMS / 256, 256>>>();
    k_compact_all<<<64, 256>>>();
    k_qkv<<<NSEL / 16, 256>>>(x, Wn, bn, Wq, bq, Wk, bk, Wv, bv);
    k_attn_tc<<<dim3(NSEL / TQ, HEADS), 256>>>();
    k_colsum_final<<<HID, 256>>>(Wo, bo, W1, b1, W2, b2, out);
}